// round 7
// baseline (speedup 1.0000x reference)
#include <cuda_runtime.h>
#include <math.h>

// ---------------- problem constants ----------------
#define TT     4096
#define DMODEL 2048
#define NH     16
#define DQK    192     // 128 nope + 64 rope
#define DNOPE  128
#define DROPE  64
#define DV     128
#define RANK   512
#define KVF    (RANK + DROPE)          // 576
#define QSTRIDE (NH * DQK)             // 3072
#define KVBSTRIDE (NH * (DNOPE + DV))  // 4096
#define OSTRIDE (NH * DV)              // 2048
#define SCALE 0.07216878364870323f     // 192^-0.5

// ---------------- scratch (no cudaMalloc allowed) ----------------
__device__ float g_q[TT * QSTRIDE];
__device__ float g_kvfull[TT * KVF];
__device__ float g_kvn[TT * RANK];
__device__ float g_kpe[TT * DROPE];
__device__ float g_kvb[TT * KVBSTRIDE];
__device__ float g_attn[TT * OSTRIDE];
__device__ float g_cos[TT * 32];
__device__ float g_sin[TT * 32];

// ---------------- tf32 / async helpers ----------------
__device__ __forceinline__ unsigned f2tf(float x) {
    unsigned u;
    asm("cvt.rna.tf32.f32 %0, %1;" : "=r"(u) : "f"(x));
    return u;
}
__device__ __forceinline__ void mma_tf32(float c[4],
    unsigned a0, unsigned a1, unsigned a2, unsigned a3,
    unsigned b0, unsigned b1)
{
    asm volatile(
        "mma.sync.aligned.m16n8k8.row.col.f32.tf32.tf32.f32 "
        "{%0,%1,%2,%3},{%4,%5,%6,%7},{%8,%9},{%0,%1,%2,%3};"
        : "+f"(c[0]), "+f"(c[1]), "+f"(c[2]), "+f"(c[3])
        : "r"(a0), "r"(a1), "r"(a2), "r"(a3), "r"(b0), "r"(b1));
}
__device__ __forceinline__ void cp16(void* sptr, const void* gptr) {
    unsigned a = (unsigned)__cvta_generic_to_shared(sptr);
    asm volatile("cp.async.ca.shared.global [%0], [%1], 16;" :: "r"(a), "l"(gptr));
}
#define CP_COMMIT() asm volatile("cp.async.commit_group;")

// =================================================================
// TF32 MMA GEMM v2 (unchanged from R6): 128 x (NFRAG*16) CTA tile,
// KC=32, double-buffered smem + register prefetch.
// =================================================================
#define SA 36

template<int NFRAG, bool ROPE>
__global__ void __launch_bounds__(256) gemm_tf32(
    const float* __restrict__ A, const float* __restrict__ B,
    float* __restrict__ C, int M, int N, int K)
{
    constexpr int BN  = NFRAG * 16;
    constexpr int ASZ = 128 * SA;
    constexpr int BSZ = BN * SA;
    extern __shared__ unsigned smemg[];
    unsigned* As = smemg;
    unsigned* Bs = smemg + 2 * ASZ;

    const int tid = threadIdx.x;
    const int lane = tid & 31, w = tid >> 5;
    const int g = lane >> 2, tig = lane & 3;
    const int bm = blockIdx.y * 128, bn = blockIdx.x * BN;
    const int m0 = (w >> 1) * 32;
    const int n0 = (w & 1) * (BN / 2);

    const int arow = tid >> 1, acs = (tid & 1) * 16;
    constexpr int TPR = 256 / BN;
    constexpr int BW  = 32 / TPR;
    constexpr int NB4 = BW / 4;
    const int brow = tid / TPR, bcs = (tid % TPR) * BW;

    const float* Ap = A + (size_t)(bm + arow) * K + acs;
    const float* Bp = B + (size_t)(bn + brow) * K + bcs;

    float4 ra[4], rb[NB4];
    float c[2][NFRAG][4] = {};

#pragma unroll
    for (int u = 0; u < 4; u++) ra[u] = *(const float4*)(Ap + u * 4);
#pragma unroll
    for (int u = 0; u < NB4; u++) rb[u] = *(const float4*)(Bp + u * 4);
#pragma unroll
    for (int u = 0; u < 4; u++) {
        uint4 t = make_uint4(f2tf(ra[u].x), f2tf(ra[u].y), f2tf(ra[u].z), f2tf(ra[u].w));
        *(uint4*)&As[arow * SA + acs + u * 4] = t;
    }
#pragma unroll
    for (int u = 0; u < NB4; u++) {
        uint4 t = make_uint4(f2tf(rb[u].x), f2tf(rb[u].y), f2tf(rb[u].z), f2tf(rb[u].w));
        *(uint4*)&Bs[brow * SA + bcs + u * 4] = t;
    }
    __syncthreads();

    int cur = 0;
    for (int k0 = 0; k0 < K; k0 += 32) {
        const bool more = (k0 + 32) < K;
        if (more) {
#pragma unroll
            for (int u = 0; u < 4; u++) ra[u] = *(const float4*)(Ap + k0 + 32 + u * 4);
#pragma unroll
            for (int u = 0; u < NB4; u++) rb[u] = *(const float4*)(Bp + k0 + 32 + u * 4);
        }
        const unsigned* Ac = As + cur * ASZ;
        const unsigned* Bc = Bs + cur * BSZ;
#pragma unroll
        for (int kk = 0; kk < 32; kk += 8) {
            unsigned a[2][4];
#pragma unroll
            for (int i = 0; i < 2; i++) {
                int r = m0 + i * 16 + g;
                a[i][0] = Ac[r * SA + kk + tig];
                a[i][1] = Ac[(r + 8) * SA + kk + tig];
                a[i][2] = Ac[r * SA + kk + tig + 4];
                a[i][3] = Ac[(r + 8) * SA + kk + tig + 4];
            }
#pragma unroll
            for (int j = 0; j < NFRAG; j++) {
                unsigned b0 = Bc[(n0 + j * 8 + g) * SA + kk + tig];
                unsigned b1 = Bc[(n0 + j * 8 + g) * SA + kk + tig + 4];
#pragma unroll
                for (int i = 0; i < 2; i++)
                    mma_tf32(c[i][j], a[i][0], a[i][1], a[i][2], a[i][3], b0, b1);
            }
        }
        if (more) {
            int nx = cur ^ 1;
#pragma unroll
            for (int u = 0; u < 4; u++) {
                uint4 t = make_uint4(f2tf(ra[u].x), f2tf(ra[u].y), f2tf(ra[u].z), f2tf(ra[u].w));
                *(uint4*)&As[nx * ASZ + arow * SA + acs + u * 4] = t;
            }
#pragma unroll
            for (int u = 0; u < NB4; u++) {
                uint4 t = make_uint4(f2tf(rb[u].x), f2tf(rb[u].y), f2tf(rb[u].z), f2tf(rb[u].w));
                *(uint4*)&Bs[nx * BSZ + brow * SA + bcs + u * 4] = t;
            }
        }
        __syncthreads();
        cur ^= 1;
    }

#pragma unroll
    for (int i = 0; i < 2; i++) {
        int r0 = bm + m0 + i * 16 + g;
#pragma unroll
        for (int j = 0; j < NFRAG; j++) {
            int cc = bn + n0 + j * 8 + tig * 2;
            float v00 = c[i][j][0], v01 = c[i][j][1];
            float v10 = c[i][j][2], v11 = c[i][j][3];
            if (ROPE) {
                int hc = cc % DQK;
                if (hc >= DNOPE) {
                    int pi = (hc - DNOPE) >> 1;
                    float c0 = g_cos[r0 * 32 + pi], s0 = g_sin[r0 * 32 + pi];
                    float t0 = v00 * c0 - v01 * s0;
                    v01 = v00 * s0 + v01 * c0; v00 = t0;
                    float c1 = g_cos[(r0 + 8) * 32 + pi], s1 = g_sin[(r0 + 8) * 32 + pi];
                    float t1 = v10 * c1 - v11 * s1;
                    v11 = v10 * s1 + v11 * c1; v10 = t1;
                }
            }
            *(float2*)&C[(size_t)r0 * N + cc] = make_float2(v00, v01);
            *(float2*)&C[(size_t)(r0 + 8) * N + cc] = make_float2(v10, v11);
        }
    }
}

// =================================================================
// RoPE tables
// =================================================================
__global__ void rope_table_kernel()
{
    int idx = blockIdx.x * blockDim.x + threadIdx.x;
    int i = idx & 31, t = idx >> 5;
    double inv = pow(10000.0, -(double)(2 * i) / 64.0);
    double sd, cd;
    sincos((double)t * inv, &sd, &cd);
    g_cos[idx] = (float)cd;
    g_sin[idx] = (float)sd;
}

// LayerNorm(kv) + RoPE(k_pe)
__global__ void ln_ropek_kernel(
    const float* __restrict__ kvf, const float* __restrict__ gamma,
    const float* __restrict__ beta, float* __restrict__ kvn,
    float* __restrict__ kpe)
{
    int row = blockIdx.x, tid = threadIdx.x;
    __shared__ float red[16];
    float a = kvf[row * KVF + tid];
    float b = kvf[row * KVF + 256 + tid];
    float s1 = a + b, s2 = a * a + b * b;
#pragma unroll
    for (int off = 16; off; off >>= 1) {
        s1 += __shfl_xor_sync(0xffffffffu, s1, off);
        s2 += __shfl_xor_sync(0xffffffffu, s2, off);
    }
    if ((tid & 31) == 0) { red[tid >> 5] = s1; red[8 + (tid >> 5)] = s2; }
    __syncthreads();
    float t1 = 0.f, t2 = 0.f;
#pragma unroll
    for (int i = 0; i < 8; i++) { t1 += red[i]; t2 += red[8 + i]; }
    float mean = t1 * (1.f / 512.f);
    float var  = t2 * (1.f / 512.f) - mean * mean;
    float rstd = rsqrtf(var + 1e-5f);
    kvn[row * RANK + tid]       = (a - mean) * rstd * gamma[tid] + beta[tid];
    kvn[row * RANK + 256 + tid] = (b - mean) * rstd * gamma[256 + tid] + beta[256 + tid];
    if (tid < 32) {
        int i = tid;
        float c = g_cos[row * 32 + i], s = g_sin[row * 32 + i];
        float x1 = kvf[row * KVF + RANK + 2 * i];
        float x2 = kvf[row * KVF + RANK + 2 * i + 1];
        kpe[row * DROPE + 2 * i]     = x1 * c - x2 * s;
        kpe[row * DROPE + 2 * i + 1] = x1 * s + x2 * c;
    }
}

// =================================================================
// Flash attention v2: cp.async double-buffered K/V, XOR-swizzled smem.
// Block = (q-tile of 64 rows, head). 256 threads = 8 warps (4x2).
// Smem: Q[64][192] (tf32), K[2][64][192] (f32), V[2][64][128] (f32),
//       S[64][68] (f32).  Total 231168 B.
// Swizzles: Q/K col^((row&7)<<2), V col^((row&3)<<3) -> conflict-free
// fragment LDS for both access patterns.
// =================================================================
#define KSZ (64 * 192)
#define VSZ (64 * 128)
#define SSP 68
#define ATTN_SMEM_BYTES ((64*192 + 2*KSZ + 2*VSZ + 64*SSP + 192) * 4)

__device__ __forceinline__ int swk(int r, int c) { return r * 192 + (c ^ ((r & 7) << 2)); }
__device__ __forceinline__ int swv(int r, int c) { return r * 128 + (c ^ ((r & 3) << 3)); }

__global__ void __launch_bounds__(256, 1) attn_kernel(
    const float* __restrict__ q, const float* __restrict__ kvb,
    const float* __restrict__ kpe, float* __restrict__ outp)
{
    extern __shared__ float sma[];
    float* Qs  = sma;                  // [64][192] pre-rounded tf32 values
    float* Ks  = Qs + 64 * 192;        // [2][64][192] raw f32
    float* Vs  = Ks + 2 * KSZ;         // [2][64][128] raw f32
    float* Ssm = Vs + 2 * VSZ;         // [64][68]
    float* m_s = Ssm + 64 * SSP;       // [64]
    float* l_s = m_s + 64;             // [64]
    float* al  = l_s + 64;             // [64]

    const int tid = threadIdx.x;
    const int lane = tid & 31, w = tid >> 5;
    const int g = lane >> 2, tig = lane & 3;
    const int m0 = (w >> 1) * 16;
    const int wn = w & 1;
    const int n0 = wn * 32;
    const int n0p = wn * 64;
    const int h  = blockIdx.y;
    const int iq = (int)(gridDim.x - 1) - (int)blockIdx.x;
    const int q0 = iq * 64;
    const int lr = tid >> 2;           // 0..63
    const int seg = tid & 3;           // 0..3

    // ---- issue cp.async for K/V tile jt into buffer buf ----
    auto issue_kv = [&](int jt, int buf) {
        int t = jt * 64 + lr;
        const float* kn = kvb + (size_t)t * KVBSTRIDE + h * 256;
        const float* kp = kpe + (size_t)t * DROPE;
        float* Kb = Ks + buf * KSZ;
        float* Vb = Vs + buf * VSZ;
#pragma unroll
        for (int u = 0; u < 12; u++) {
            int k = seg * 48 + u * 4;
            const float* src = (k < 128) ? (kn + k) : (kp + (k - 128));
            cp16(&Kb[swk(lr, k)], src);
        }
        const float* vp = kn + 128;
#pragma unroll
        for (int u = 0; u < 8; u++) {
            int cI = seg * 32 + u * 4;
            cp16(&Vb[swv(lr, cI)], vp + cI);
        }
        CP_COMMIT();
    };

    // prologue: Q tile (rounded to tf32 at store) + first K/V tile
    issue_kv(0, 0);
    {
        const float* src = q + (size_t)(q0 + lr) * QSTRIDE + h * DQK + seg * 48;
#pragma unroll
        for (int u = 0; u < 12; u++) {
            float4 v = *(const float4*)(src + u * 4);
            uint4 t = make_uint4(f2tf(v.x), f2tf(v.y), f2tf(v.z), f2tf(v.w));
            *(uint4*)&Qs[swk(lr, seg * 48 + u * 4)] = t;
        }
    }
    if (tid < 64) { m_s[tid] = -INFINITY; l_s[tid] = 0.f; }

    float o[8][4] = {};

    for (int jt = 0; jt <= iq; jt++) {
        __syncthreads();   // all reads of the buffer being overwritten are done

        if (jt < iq) {
            issue_kv(jt + 1, (jt + 1) & 1);
            asm volatile("cp.async.wait_group 1;");
        } else {
            asm volatile("cp.async.wait_group 0;");
        }
        __syncthreads();   // current tile visible to all threads

        const float* Kc = Ks + (jt & 1) * KSZ;
        const float* Vc = Vs + (jt & 1) * VSZ;

        // ---- S = Q K^T (warp tile 16x32, K=192) ----
        float s[4][4] = {};
#pragma unroll
        for (int k0 = 0; k0 < 192; k0 += 8) {
            unsigned a0 = __float_as_uint(Qs[swk(m0 + g, k0 + tig)]);
            unsigned a1 = __float_as_uint(Qs[swk(m0 + 8 + g, k0 + tig)]);
            unsigned a2 = __float_as_uint(Qs[swk(m0 + g, k0 + tig + 4)]);
            unsigned a3 = __float_as_uint(Qs[swk(m0 + 8 + g, k0 + tig + 4)]);
#pragma unroll
            for (int j = 0; j < 4; j++) {
                unsigned b0 = f2tf(Kc[swk(n0 + j * 8 + g, k0 + tig)]);
                unsigned b1 = f2tf(Kc[swk(n0 + j * 8 + g, k0 + tig + 4)]);
                mma_tf32(s[j], a0, a1, a2, a3, b0, b1);
            }
        }
#pragma unroll
        for (int j = 0; j < 4; j++) {
            int col = n0 + j * 8 + tig * 2;
            int gc0 = jt * 64 + col, gc1 = gc0 + 1;
            int gr0 = q0 + m0 + g, gr1 = gr0 + 8;
            float v0 = (gr0 >= gc0) ? s[j][0] * SCALE : -INFINITY;
            float v1 = (gr0 >= gc1) ? s[j][1] * SCALE : -INFINITY;
            float v2 = (gr1 >= gc0) ? s[j][2] * SCALE : -INFINITY;
            float v3 = (gr1 >= gc1) ? s[j][3] * SCALE : -INFINITY;
            *(float2*)&Ssm[(m0 + g) * SSP + col]     = make_float2(v0, v1);
            *(float2*)&Ssm[(m0 + 8 + g) * SSP + col] = make_float2(v2, v3);
        }
        __syncthreads();

        // ---- online softmax: 4 lanes per row, shfl reductions ----
        {
            int r = lr;
            float* row = &Ssm[r * SSP + seg * 16];
            float mx = -INFINITY;
#pragma unroll
            for (int cI = 0; cI < 16; cI++) mx = fmaxf(mx, row[cI]);
            mx = fmaxf(mx, __shfl_xor_sync(0xffffffffu, mx, 1));
            mx = fmaxf(mx, __shfl_xor_sync(0xffffffffu, mx, 2));
            float mo = m_s[r];
            float mn = fmaxf(mo, mx);
            float alpha = __expf(mo - mn);
            float sum = 0.f;
#pragma unroll
            for (int cI = 0; cI < 16; cI++) {
                float p = __expf(row[cI] - mn);
                row[cI] = p;
                sum += p;
            }
            sum += __shfl_xor_sync(0xffffffffu, sum, 1);
            sum += __shfl_xor_sync(0xffffffffu, sum, 2);
            if (seg == 0) {
                m_s[r] = mn;
                al[r]  = alpha;
                l_s[r] = l_s[r] * alpha + sum;
            }
        }
        __syncthreads();

        // ---- O = O*alpha + P @ V (warp tile 16x64, K=64) ----
        {
            float av0 = al[m0 + g], av1 = al[m0 + 8 + g];
#pragma unroll
            for (int nt = 0; nt < 8; nt++) {
                o[nt][0] *= av0; o[nt][1] *= av0;
                o[nt][2] *= av1; o[nt][3] *= av1;
            }
        }
#pragma unroll
        for (int k0 = 0; k0 < 64; k0 += 8) {
            unsigned a0 = f2tf(Ssm[(m0 + g) * SSP + k0 + tig]);
            unsigned a1 = f2tf(Ssm[(m0 + 8 + g) * SSP + k0 + tig]);
            unsigned a2 = f2tf(Ssm[(m0 + g) * SSP + k0 + tig + 4]);
            unsigned a3 = f2tf(Ssm[(m0 + 8 + g) * SSP + k0 + tig + 4]);
#pragma unroll
            for (int nt = 0; nt < 8; nt++) {
                unsigned b0 = f2tf(Vc[swv(k0 + tig, n0p + nt * 8 + g)]);
                unsigned b1 = f2tf(Vc[swv(k0 + tig + 4, n0p + nt * 8 + g)]);
                mma_tf32(o[nt], a0, a1, a2, a3, b0, b1);
            }
        }
    }
    __syncthreads();   // l_s complete

    {
        float inv0 = 1.f / l_s[m0 + g];
        float inv1 = 1.f / l_s[m0 + 8 + g];
        float* d0 = outp + (size_t)(q0 + m0 + g) * OSTRIDE + h * DV + n0p;
        float* d1 = outp + (size_t)(q0 + m0 + 8 + g) * OSTRIDE + h * DV + n0p;
#pragma unroll
        for (int nt = 0; nt < 8; nt++) {
            int cc = nt * 8 + tig * 2;
            *(float2*)(d0 + cc) = make_float2(o[nt][0] * inv0, o[nt][1] * inv0);
            *(float2*)(d1 + cc) = make_float2(o[nt][2] * inv1, o[nt][3] * inv1);
        }
    }
}

// =================================================================
// launch
// =================================================================
#define GSM8 (2 * (128 * SA + 128 * SA) * 4)
#define GSM4 (2 * (128 * SA + 64 * SA) * 4)

extern "C" void kernel_launch(void* const* d_in, const int* in_sizes, int n_in,
                              void* d_out, int out_size)
{
    const float* x     = (const float*)d_in[0];
    const float* wq    = (const float*)d_in[1];
    const float* wkv_a = (const float*)d_in[2];
    const float* gamma = (const float*)d_in[3];
    const float* beta  = (const float*)d_in[4];
    const float* wkv_b = (const float*)d_in[5];
    const float* wo    = (const float*)d_in[6];
    float* out = (float*)d_out;

    float *gq, *gkvf, *gkvn, *gkpe, *gkvb, *gattn;
    cudaGetSymbolAddress((void**)&gq,    g_q);
    cudaGetSymbolAddress((void**)&gkvf,  g_kvfull);
    cudaGetSymbolAddress((void**)&gkvn,  g_kvn);
    cudaGetSymbolAddress((void**)&gkpe,  g_kpe);
    cudaGetSymbolAddress((void**)&gkvb,  g_kvb);
    cudaGetSymbolAddress((void**)&gattn, g_attn);

    cudaFuncSetAttribute(gemm_tf32<8, true>,
                         cudaFuncAttributeMaxDynamicSharedMemorySize, GSM8);
    cudaFuncSetAttribute(gemm_tf32<8, false>,
                         cudaFuncAttributeMaxDynamicSharedMemorySize, GSM8);
    cudaFuncSetAttribute(gemm_tf32<4, false>,
                         cudaFuncAttributeMaxDynamicSharedMemorySize, GSM4);
    cudaFuncSetAttribute(attn_kernel,
                         cudaFuncAttributeMaxDynamicSharedMemorySize, ATTN_SMEM_BYTES);

    // rope tables
    rope_table_kernel<<<(TT * 32) / 256, 256>>>();
    // q = x @ wq^T (+fused rope on q_pe)   (4096 x 3072, K=2048)
    gemm_tf32<8, true><<<dim3(3072 / 128, TT / 128), 256, GSM8>>>(
        x, wq, gq, TT, 3072, DMODEL);
    // kv_full = x @ wkv_a^T  (4096 x 576, K=2048)
    gemm_tf32<4, false><<<dim3(KVF / 64, TT / 128), 256, GSM4>>>(
        x, wkv_a, gkvf, TT, KVF, DMODEL);
    // layernorm(kv) + rope(k_pe)
    ln_ropek_kernel<<<TT, 256>>>(gkvf, gamma, beta, gkvn, gkpe);
    // kvb = kvn @ wkv_b^T  (4096 x 4096, K=512)
    gemm_tf32<8, false><<<dim3(KVBSTRIDE / 128, TT / 128), 256, GSM8>>>(
        gkvn, wkv_b, gkvb, TT, KVBSTRIDE, RANK);
    // attention
    attn_kernel<<<dim3(TT / 64, NH), 256, ATTN_SMEM_BYTES>>>(gq, gkvb, gkpe, gattn);
    // out = attn @ wo^T  (4096 x 2048, K=2048)
    gemm_tf32<8, false><<<dim3(DMODEL / 128, TT / 128), 256, GSM8>>>(
        gattn, wo, out, TT, DMODEL, DMODEL);
}

// round 8
// speedup vs baseline: 1.1611x; 1.1611x over previous
#include <cuda_runtime.h>
#include <math.h>

// ---------------- problem constants ----------------
#define TT     4096
#define DMODEL 2048
#define NH     16
#define DQK    192     // 128 nope + 64 rope
#define DNOPE  128
#define DROPE  64
#define DV     128
#define RANK   512
#define KVF    (RANK + DROPE)          // 576
#define QSTRIDE (NH * DQK)             // 3072
#define KVBSTRIDE (NH * (DNOPE + DV))  // 4096
#define OSTRIDE (NH * DV)              // 2048
#define SCALE 0.07216878364870323f     // 192^-0.5

// ---------------- scratch (no cudaMalloc allowed) ----------------
__device__ float g_q[TT * QSTRIDE];
__device__ float g_kvfull[TT * KVF];
__device__ float g_kvn[TT * RANK];
__device__ float g_kpe[TT * DROPE];
__device__ float g_kvb[TT * KVBSTRIDE];
__device__ float g_attn[TT * OSTRIDE];
__device__ float g_cos[TT * 32];
__device__ float g_sin[TT * 32];

// ---------------- tf32 helpers ----------------
__device__ __forceinline__ unsigned f2tf(float x) {
    unsigned u;
    asm("cvt.rna.tf32.f32 %0, %1;" : "=r"(u) : "f"(x));
    return u;
}
__device__ __forceinline__ void mma_tf32(float c[4],
    unsigned a0, unsigned a1, unsigned a2, unsigned a3,
    unsigned b0, unsigned b1)
{
    asm volatile(
        "mma.sync.aligned.m16n8k8.row.col.f32.tf32.tf32.f32 "
        "{%0,%1,%2,%3},{%4,%5,%6,%7},{%8,%9},{%0,%1,%2,%3};"
        : "+f"(c[0]), "+f"(c[1]), "+f"(c[2]), "+f"(c[3])
        : "r"(a0), "r"(a1), "r"(a2), "r"(a3), "r"(b0), "r"(b1));
}

// =================================================================
// TF32 MMA GEMM v2 (R6, unchanged): 128 x (NFRAG*16) CTA tile, KC=32,
// double-buffered smem + register prefetch.
// =================================================================
#define SA 36

template<int NFRAG, bool ROPE>
__global__ void __launch_bounds__(256) gemm_tf32(
    const float* __restrict__ A, const float* __restrict__ B,
    float* __restrict__ C, int M, int N, int K)
{
    constexpr int BN  = NFRAG * 16;
    constexpr int ASZ = 128 * SA;
    constexpr int BSZ = BN * SA;
    extern __shared__ unsigned smemg[];
    unsigned* As = smemg;
    unsigned* Bs = smemg + 2 * ASZ;

    const int tid = threadIdx.x;
    const int lane = tid & 31, w = tid >> 5;
    const int g = lane >> 2, tig = lane & 3;
    const int bm = blockIdx.y * 128, bn = blockIdx.x * BN;
    const int m0 = (w >> 1) * 32;
    const int n0 = (w & 1) * (BN / 2);

    const int arow = tid >> 1, acs = (tid & 1) * 16;
    constexpr int TPR = 256 / BN;
    constexpr int BW  = 32 / TPR;
    constexpr int NB4 = BW / 4;
    const int brow = tid / TPR, bcs = (tid % TPR) * BW;

    const float* Ap = A + (size_t)(bm + arow) * K + acs;
    const float* Bp = B + (size_t)(bn + brow) * K + bcs;

    float4 ra[4], rb[NB4];
    float c[2][NFRAG][4] = {};

#pragma unroll
    for (int u = 0; u < 4; u++) ra[u] = *(const float4*)(Ap + u * 4);
#pragma unroll
    for (int u = 0; u < NB4; u++) rb[u] = *(const float4*)(Bp + u * 4);
#pragma unroll
    for (int u = 0; u < 4; u++) {
        uint4 t = make_uint4(f2tf(ra[u].x), f2tf(ra[u].y), f2tf(ra[u].z), f2tf(ra[u].w));
        *(uint4*)&As[arow * SA + acs + u * 4] = t;
    }
#pragma unroll
    for (int u = 0; u < NB4; u++) {
        uint4 t = make_uint4(f2tf(rb[u].x), f2tf(rb[u].y), f2tf(rb[u].z), f2tf(rb[u].w));
        *(uint4*)&Bs[brow * SA + bcs + u * 4] = t;
    }
    __syncthreads();

    int cur = 0;
    for (int k0 = 0; k0 < K; k0 += 32) {
        const bool more = (k0 + 32) < K;
        if (more) {
#pragma unroll
            for (int u = 0; u < 4; u++) ra[u] = *(const float4*)(Ap + k0 + 32 + u * 4);
#pragma unroll
            for (int u = 0; u < NB4; u++) rb[u] = *(const float4*)(Bp + k0 + 32 + u * 4);
        }
        const unsigned* Ac = As + cur * ASZ;
        const unsigned* Bc = Bs + cur * BSZ;
#pragma unroll
        for (int kk = 0; kk < 32; kk += 8) {
            unsigned a[2][4];
#pragma unroll
            for (int i = 0; i < 2; i++) {
                int r = m0 + i * 16 + g;
                a[i][0] = Ac[r * SA + kk + tig];
                a[i][1] = Ac[(r + 8) * SA + kk + tig];
                a[i][2] = Ac[r * SA + kk + tig + 4];
                a[i][3] = Ac[(r + 8) * SA + kk + tig + 4];
            }
#pragma unroll
            for (int j = 0; j < NFRAG; j++) {
                unsigned b0 = Bc[(n0 + j * 8 + g) * SA + kk + tig];
                unsigned b1 = Bc[(n0 + j * 8 + g) * SA + kk + tig + 4];
#pragma unroll
                for (int i = 0; i < 2; i++)
                    mma_tf32(c[i][j], a[i][0], a[i][1], a[i][2], a[i][3], b0, b1);
            }
        }
        if (more) {
            int nx = cur ^ 1;
#pragma unroll
            for (int u = 0; u < 4; u++) {
                uint4 t = make_uint4(f2tf(ra[u].x), f2tf(ra[u].y), f2tf(ra[u].z), f2tf(ra[u].w));
                *(uint4*)&As[nx * ASZ + arow * SA + acs + u * 4] = t;
            }
#pragma unroll
            for (int u = 0; u < NB4; u++) {
                uint4 t = make_uint4(f2tf(rb[u].x), f2tf(rb[u].y), f2tf(rb[u].z), f2tf(rb[u].w));
                *(uint4*)&Bs[nx * BSZ + brow * SA + bcs + u * 4] = t;
            }
        }
        __syncthreads();
        cur ^= 1;
    }

#pragma unroll
    for (int i = 0; i < 2; i++) {
        int r0 = bm + m0 + i * 16 + g;
#pragma unroll
        for (int j = 0; j < NFRAG; j++) {
            int cc = bn + n0 + j * 8 + tig * 2;
            float v00 = c[i][j][0], v01 = c[i][j][1];
            float v10 = c[i][j][2], v11 = c[i][j][3];
            if (ROPE) {
                int hc = cc % DQK;
                if (hc >= DNOPE) {
                    int pi = (hc - DNOPE) >> 1;
                    float c0 = g_cos[r0 * 32 + pi], s0 = g_sin[r0 * 32 + pi];
                    float t0 = v00 * c0 - v01 * s0;
                    v01 = v00 * s0 + v01 * c0; v00 = t0;
                    float c1 = g_cos[(r0 + 8) * 32 + pi], s1 = g_sin[(r0 + 8) * 32 + pi];
                    float t1 = v10 * c1 - v11 * s1;
                    v11 = v10 * s1 + v11 * c1; v10 = t1;
                }
            }
            *(float2*)&C[(size_t)r0 * N + cc] = make_float2(v00, v01);
            *(float2*)&C[(size_t)(r0 + 8) * N + cc] = make_float2(v10, v11);
        }
    }
}

// =================================================================
// RoPE tables
// =================================================================
__global__ void rope_table_kernel()
{
    int idx = blockIdx.x * blockDim.x + threadIdx.x;
    int i = idx & 31, t = idx >> 5;
    double inv = pow(10000.0, -(double)(2 * i) / 64.0);
    double sd, cd;
    sincos((double)t * inv, &sd, &cd);
    g_cos[idx] = (float)cd;
    g_sin[idx] = (float)sd;
}

// LayerNorm(kv) + RoPE(k_pe)
__global__ void ln_ropek_kernel(
    const float* __restrict__ kvf, const float* __restrict__ gamma,
    const float* __restrict__ beta, float* __restrict__ kvn,
    float* __restrict__ kpe)
{
    int row = blockIdx.x, tid = threadIdx.x;
    __shared__ float red[16];
    float a = kvf[row * KVF + tid];
    float b = kvf[row * KVF + 256 + tid];
    float s1 = a + b, s2 = a * a + b * b;
#pragma unroll
    for (int off = 16; off; off >>= 1) {
        s1 += __shfl_xor_sync(0xffffffffu, s1, off);
        s2 += __shfl_xor_sync(0xffffffffu, s2, off);
    }
    if ((tid & 31) == 0) { red[tid >> 5] = s1; red[8 + (tid >> 5)] = s2; }
    __syncthreads();
    float t1 = 0.f, t2 = 0.f;
#pragma unroll
    for (int i = 0; i < 8; i++) { t1 += red[i]; t2 += red[8 + i]; }
    float mean = t1 * (1.f / 512.f);
    float var  = t2 * (1.f / 512.f) - mean * mean;
    float rstd = rsqrtf(var + 1e-5f);
    kvn[row * RANK + tid]       = (a - mean) * rstd * gamma[tid] + beta[tid];
    kvn[row * RANK + 256 + tid] = (b - mean) * rstd * gamma[256 + tid] + beta[256 + tid];
    if (tid < 32) {
        int i = tid;
        float c = g_cos[row * 32 + i], s = g_sin[row * 32 + i];
        float x1 = kvf[row * KVF + RANK + 2 * i];
        float x2 = kvf[row * KVF + RANK + 2 * i + 1];
        kpe[row * DROPE + 2 * i]     = x1 * c - x2 * s;
        kpe[row * DROPE + 2 * i + 1] = x1 * s + x2 * c;
    }
}

// =================================================================
// Flash attention v3: q-tile 128 rows x kv-tile 64 (2x K/V reuse vs R6).
// Block = (q-tile, head). 256 threads = 8 warps, all in M (16 rows each);
// each warp covers full N (64 for QK, 128 for PV).
// Smem: Q[128][196] tf32, K[64][196] tf32, V[64][136] tf32, S[128][68] f32.
// cvt to tf32 at store time (R7 lesson: keep cvt off the MMA critical path).
// =================================================================
#define SQ  196
#define SV  136
#define SSP 68
#define QR  128
#define ATTN_SMEM_BYTES ((QR*SQ + 64*SQ + 64*SV + QR*SSP + 3*QR) * 4)

__global__ void __launch_bounds__(256, 1) attn_kernel(
    const float* __restrict__ q, const float* __restrict__ kvb,
    const float* __restrict__ kpe, float* __restrict__ outp)
{
    extern __shared__ unsigned sm[];
    unsigned* Qs = sm;                    // [128][196] tf32 bits
    unsigned* Ks = Qs + QR * SQ;          // [64][196]
    unsigned* Vs = Ks + 64 * SQ;          // [64][136]
    float* Ssm = (float*)(Vs + 64 * SV);  // [128][68]
    float* m_s = Ssm + QR * SSP;          // [128]
    float* l_s = m_s + QR;                // [128]
    float* al  = l_s + QR;                // [128]

    const int tid = threadIdx.x;
    const int lane = tid & 31, w = tid >> 5;
    const int g = lane >> 2, tig = lane & 3;
    const int m0 = w * 16;                 // warp q-row base (0..112)
    const int h  = blockIdx.y;
    const int iq = (int)(gridDim.x - 1) - (int)blockIdx.x; // big tiles first
    const int q0 = iq * QR;
    const int lr = tid >> 2;               // 0..63   (K/V loads)
    const int seg = tid & 3;               // 0..3
    const int qr = tid >> 1;               // 0..127  (Q load / softmax)
    const int qs = tid & 1;                // 0..1

    // ---- load Q tile (128 x 192), row-major tf32 ----
    {
        const float* src = q + (size_t)(q0 + qr) * QSTRIDE + h * DQK + qs * 96;
#pragma unroll
        for (int u = 0; u < 24; u++) {
            float4 v = *(const float4*)(src + u * 4);
            uint4 t = make_uint4(f2tf(v.x), f2tf(v.y), f2tf(v.z), f2tf(v.w));
            *(uint4*)&Qs[qr * SQ + qs * 96 + u * 4] = t;
        }
    }
    if (tid < QR) { m_s[tid] = -INFINITY; l_s[tid] = 0.f; }

    float o[16][4] = {};   // PV accumulators: 16 n-frags x (2 rows x 2 cols)

    const int jmax = 2 * iq + 1;
    for (int jt = 0; jt <= jmax; jt++) {
        __syncthreads();   // prev PV reads done; smem reuse safe (and init on iter 0)

        // ---- load K (k_nope | k_pe) + V tiles, tf32 at store ----
        {
            int t = jt * 64 + lr;
            const float* kn = kvb + (size_t)t * KVBSTRIDE + h * 256;
            const float* kp = kpe + (size_t)t * DROPE;
#pragma unroll
            for (int u = 0; u < 12; u++) {
                int k = seg * 48 + u * 4;
                float4 v = (k < 128) ? *(const float4*)(kn + k)
                                     : *(const float4*)(kp + (k - 128));
                uint4 tt = make_uint4(f2tf(v.x), f2tf(v.y), f2tf(v.z), f2tf(v.w));
                *(uint4*)&Ks[lr * SQ + k] = tt;
            }
            const float* vp = kn + 128;
#pragma unroll
            for (int u = 0; u < 8; u++) {
                int cidx = seg * 32 + u * 4;
                float4 v = *(const float4*)(vp + cidx);
                uint4 tt = make_uint4(f2tf(v.x), f2tf(v.y), f2tf(v.z), f2tf(v.w));
                *(uint4*)&Vs[lr * SV + cidx] = tt;
            }
        }
        __syncthreads();

        // ---- S = Q K^T (warp tile 16x64, K=192) ----
        float s[8][4] = {};
#pragma unroll
        for (int k0 = 0; k0 < 192; k0 += 8) {
            unsigned a0 = Qs[(m0 + g) * SQ + k0 + tig];
            unsigned a1 = Qs[(m0 + 8 + g) * SQ + k0 + tig];
            unsigned a2 = Qs[(m0 + g) * SQ + k0 + tig + 4];
            unsigned a3 = Qs[(m0 + 8 + g) * SQ + k0 + tig + 4];
#pragma unroll
            for (int j = 0; j < 8; j++) {
                unsigned b0 = Ks[(j * 8 + g) * SQ + k0 + tig];
                unsigned b1 = Ks[(j * 8 + g) * SQ + k0 + tig + 4];
                mma_tf32(s[j], a0, a1, a2, a3, b0, b1);
            }
        }
#pragma unroll
        for (int j = 0; j < 8; j++) {
            int col = j * 8 + tig * 2;
            int gc0 = jt * 64 + col, gc1 = gc0 + 1;
            int gr0 = q0 + m0 + g, gr1 = gr0 + 8;
            float v0 = (gr0 >= gc0) ? s[j][0] * SCALE : -INFINITY;
            float v1 = (gr0 >= gc1) ? s[j][1] * SCALE : -INFINITY;
            float v2 = (gr1 >= gc0) ? s[j][2] * SCALE : -INFINITY;
            float v3 = (gr1 >= gc1) ? s[j][3] * SCALE : -INFINITY;
            *(float2*)&Ssm[(m0 + g) * SSP + col]     = make_float2(v0, v1);
            *(float2*)&Ssm[(m0 + 8 + g) * SSP + col] = make_float2(v2, v3);
        }
        __syncthreads();

        // ---- online softmax: 2 lanes per row (32 cols each), shfl reduce ----
        {
            float* row = &Ssm[qr * SSP + qs * 32];
            float mx = -INFINITY;
#pragma unroll
            for (int cI = 0; cI < 32; cI++) mx = fmaxf(mx, row[cI]);
            mx = fmaxf(mx, __shfl_xor_sync(0xffffffffu, mx, 1));
            float mo = m_s[qr];
            float mn = fmaxf(mo, mx);
            float alpha = __expf(mo - mn);
            float sum = 0.f;
#pragma unroll
            for (int cI = 0; cI < 32; cI++) {
                float p = __expf(row[cI] - mn);
                row[cI] = p;
                sum += p;
            }
            sum += __shfl_xor_sync(0xffffffffu, sum, 1);
            if (qs == 0) {
                m_s[qr] = mn;
                al[qr]  = alpha;
                l_s[qr] = l_s[qr] * alpha + sum;
            }
        }
        __syncthreads();

        // ---- O = O*alpha + P @ V (warp tile 16x128, K=64) ----
        {
            float av0 = al[m0 + g], av1 = al[m0 + 8 + g];
#pragma unroll
            for (int nt = 0; nt < 16; nt++) {
                o[nt][0] *= av0; o[nt][1] *= av0;
                o[nt][2] *= av1; o[nt][3] *= av1;
            }
        }
#pragma unroll
        for (int k0 = 0; k0 < 64; k0 += 8) {
            unsigned a0 = f2tf(Ssm[(m0 + g) * SSP + k0 + tig]);
            unsigned a1 = f2tf(Ssm[(m0 + 8 + g) * SSP + k0 + tig]);
            unsigned a2 = f2tf(Ssm[(m0 + g) * SSP + k0 + tig + 4]);
            unsigned a3 = f2tf(Ssm[(m0 + 8 + g) * SSP + k0 + tig + 4]);
#pragma unroll
            for (int nt = 0; nt < 16; nt++) {
                unsigned b0 = Vs[(k0 + tig) * SV + nt * 8 + g];
                unsigned b1 = Vs[(k0 + tig + 4) * SV + nt * 8 + g];
                mma_tf32(o[nt], a0, a1, a2, a3, b0, b1);
            }
        }
    }
    __syncthreads();   // l_s complete

    {
        float inv0 = 1.f / l_s[m0 + g];
        float inv1 = 1.f / l_s[m0 + 8 + g];
        float* d0 = outp + (size_t)(q0 + m0 + g) * OSTRIDE + h * DV;
        float* d1 = outp + (size_t)(q0 + m0 + 8 + g) * OSTRIDE + h * DV;
#pragma unroll
        for (int nt = 0; nt < 16; nt++) {
            int cc = nt * 8 + tig * 2;
            *(float2*)(d0 + cc) = make_float2(o[nt][0] * inv0, o[nt][1] * inv0);
            *(float2*)(d1 + cc) = make_float2(o[nt][2] * inv1, o[nt][3] * inv1);
        }
    }
}

// =================================================================
// launch
// =================================================================
#define GSM8 (2 * (128 * SA + 128 * SA) * 4)
#define GSM4 (2 * (128 * SA + 64 * SA) * 4)

extern "C" void kernel_launch(void* const* d_in, const int* in_sizes, int n_in,
                              void* d_out, int out_size)
{
    const float* x     = (const float*)d_in[0];
    const float* wq    = (const float*)d_in[1];
    const float* wkv_a = (const float*)d_in[2];
    const float* gamma = (const float*)d_in[3];
    const float* beta  = (const float*)d_in[4];
    const float* wkv_b = (const float*)d_in[5];
    const float* wo    = (const float*)d_in[6];
    float* out = (float*)d_out;

    float *gq, *gkvf, *gkvn, *gkpe, *gkvb, *gattn;
    cudaGetSymbolAddress((void**)&gq,    g_q);
    cudaGetSymbolAddress((void**)&gkvf,  g_kvfull);
    cudaGetSymbolAddress((void**)&gkvn,  g_kvn);
    cudaGetSymbolAddress((void**)&gkpe,  g_kpe);
    cudaGetSymbolAddress((void**)&gkvb,  g_kvb);
    cudaGetSymbolAddress((void**)&gattn, g_attn);

    cudaFuncSetAttribute(gemm_tf32<8, true>,
                         cudaFuncAttributeMaxDynamicSharedMemorySize, GSM8);
    cudaFuncSetAttribute(gemm_tf32<8, false>,
                         cudaFuncAttributeMaxDynamicSharedMemorySize, GSM8);
    cudaFuncSetAttribute(gemm_tf32<4, false>,
                         cudaFuncAttributeMaxDynamicSharedMemorySize, GSM4);
    cudaFuncSetAttribute(attn_kernel,
                         cudaFuncAttributeMaxDynamicSharedMemorySize, ATTN_SMEM_BYTES);

    // rope tables
    rope_table_kernel<<<(TT * 32) / 256, 256>>>();
    // q = x @ wq^T (+fused rope on q_pe)   (4096 x 3072, K=2048)
    gemm_tf32<8, true><<<dim3(3072 / 128, TT / 128), 256, GSM8>>>(
        x, wq, gq, TT, 3072, DMODEL);
    // kv_full = x @ wkv_a^T  (4096 x 576, K=2048)
    gemm_tf32<4, false><<<dim3(KVF / 64, TT / 128), 256, GSM4>>>(
        x, wkv_a, gkvf, TT, KVF, DMODEL);
    // layernorm(kv) + rope(k_pe)
    ln_ropek_kernel<<<TT, 256>>>(gkvf, gamma, beta, gkvn, gkpe);
    // kvb = kvn @ wkv_b^T  (4096 x 4096, K=512)
    gemm_tf32<8, false><<<dim3(KVBSTRIDE / 128, TT / 128), 256, GSM8>>>(
        gkvn, wkv_b, gkvb, TT, KVBSTRIDE, RANK);
    // attention (q-tile 128)
    attn_kernel<<<dim3(TT / QR, NH), 256, ATTN_SMEM_BYTES>>>(gq, gkvb, gkpe, gattn);
    // out = attn @ wo^T  (4096 x 2048, K=2048)
    gemm_tf32<8, false><<<dim3(DMODEL / 128, TT / 128), 256, GSM8>>>(
        gattn, wo, out, TT, DMODEL, DMODEL);
}

// round 9
// speedup vs baseline: 1.1861x; 1.0216x over previous
#include <cuda_runtime.h>
#include <math.h>

// ---------------- problem constants ----------------
#define TT     4096
#define DMODEL 2048
#define NH     16
#define DQK    192     // 128 nope + 64 rope
#define DNOPE  128
#define DROPE  64
#define DV     128
#define RANK   512
#define KVF    (RANK + DROPE)          // 576
#define QSTRIDE (NH * DQK)             // 3072
#define KVBSTRIDE (NH * (DNOPE + DV))  // 4096
#define OSTRIDE (NH * DV)              // 2048
#define SCALE 0.07216878364870323f     // 192^-0.5

// ---------------- scratch (no cudaMalloc allowed) ----------------
__device__ float g_q[TT * QSTRIDE];
__device__ float g_kvfull[TT * KVF];
__device__ float g_kvn[TT * RANK];
__device__ float g_kpe[TT * DROPE];
__device__ float g_kvb[TT * KVBSTRIDE];
__device__ float g_attn[TT * OSTRIDE];
__device__ float g_cos[TT * 32];
__device__ float g_sin[TT * 32];

// ---------------- tf32 helpers ----------------
__device__ __forceinline__ unsigned f2tf(float x) {
    unsigned u;
    asm("cvt.rna.tf32.f32 %0, %1;" : "=r"(u) : "f"(x));
    return u;
}
__device__ __forceinline__ void mma_tf32(float c[4],
    unsigned a0, unsigned a1, unsigned a2, unsigned a3,
    unsigned b0, unsigned b1)
{
    asm volatile(
        "mma.sync.aligned.m16n8k8.row.col.f32.tf32.tf32.f32 "
        "{%0,%1,%2,%3},{%4,%5,%6,%7},{%8,%9},{%0,%1,%2,%3};"
        : "+f"(c[0]), "+f"(c[1]), "+f"(c[2]), "+f"(c[3])
        : "r"(a0), "r"(a1), "r"(a2), "r"(a3), "r"(b0), "r"(b1));
}

// =================================================================
// TF32 MMA GEMM: 128 x (NFRAG*16) CTA tile, KC=32, double-buffered
// smem + register prefetch. launch_bounds(256,2) -> <=128 regs so two
// CTAs co-reside per SM (cross-CTA latency hiding of sync/LDG tails).
// =================================================================
#define SA 36

template<int NFRAG, bool ROPE>
__global__ void __launch_bounds__(256, 2) gemm_tf32(
    const float* __restrict__ A, const float* __restrict__ B,
    float* __restrict__ C, int M, int N, int K)
{
    constexpr int BN  = NFRAG * 16;
    constexpr int ASZ = 128 * SA;
    constexpr int BSZ = BN * SA;
    extern __shared__ unsigned smemg[];
    unsigned* As = smemg;
    unsigned* Bs = smemg + 2 * ASZ;

    const int tid = threadIdx.x;
    const int lane = tid & 31, w = tid >> 5;
    const int g = lane >> 2, tig = lane & 3;
    const int bm = blockIdx.y * 128, bn = blockIdx.x * BN;
    const int m0 = (w >> 1) * 32;
    const int n0 = (w & 1) * (BN / 2);

    const int arow = tid >> 1, acs = (tid & 1) * 16;
    constexpr int TPR = 256 / BN;
    constexpr int BW  = 32 / TPR;
    constexpr int NB4 = BW / 4;
    const int brow = tid / TPR, bcs = (tid % TPR) * BW;

    const float* Ap = A + (size_t)(bm + arow) * K + acs;
    const float* Bp = B + (size_t)(bn + brow) * K + bcs;

    float4 ra[4], rb[NB4];
    float c[2][NFRAG][4] = {};

#pragma unroll
    for (int u = 0; u < 4; u++) ra[u] = *(const float4*)(Ap + u * 4);
#pragma unroll
    for (int u = 0; u < NB4; u++) rb[u] = *(const float4*)(Bp + u * 4);
#pragma unroll
    for (int u = 0; u < 4; u++) {
        uint4 t = make_uint4(f2tf(ra[u].x), f2tf(ra[u].y), f2tf(ra[u].z), f2tf(ra[u].w));
        *(uint4*)&As[arow * SA + acs + u * 4] = t;
    }
#pragma unroll
    for (int u = 0; u < NB4; u++) {
        uint4 t = make_uint4(f2tf(rb[u].x), f2tf(rb[u].y), f2tf(rb[u].z), f2tf(rb[u].w));
        *(uint4*)&Bs[brow * SA + bcs + u * 4] = t;
    }
    __syncthreads();

    int cur = 0;
    for (int k0 = 0; k0 < K; k0 += 32) {
        const bool more = (k0 + 32) < K;
        if (more) {
#pragma unroll
            for (int u = 0; u < 4; u++) ra[u] = *(const float4*)(Ap + k0 + 32 + u * 4);
#pragma unroll
            for (int u = 0; u < NB4; u++) rb[u] = *(const float4*)(Bp + k0 + 32 + u * 4);
        }
        const unsigned* Ac = As + cur * ASZ;
        const unsigned* Bc = Bs + cur * BSZ;
#pragma unroll
        for (int kk = 0; kk < 32; kk += 8) {
            unsigned a[2][4];
#pragma unroll
            for (int i = 0; i < 2; i++) {
                int r = m0 + i * 16 + g;
                a[i][0] = Ac[r * SA + kk + tig];
                a[i][1] = Ac[(r + 8) * SA + kk + tig];
                a[i][2] = Ac[r * SA + kk + tig + 4];
                a[i][3] = Ac[(r + 8) * SA + kk + tig + 4];
            }
#pragma unroll
            for (int j = 0; j < NFRAG; j++) {
                unsigned b0 = Bc[(n0 + j * 8 + g) * SA + kk + tig];
                unsigned b1 = Bc[(n0 + j * 8 + g) * SA + kk + tig + 4];
#pragma unroll
                for (int i = 0; i < 2; i++)
                    mma_tf32(c[i][j], a[i][0], a[i][1], a[i][2], a[i][3], b0, b1);
            }
        }
        if (more) {
            int nx = cur ^ 1;
#pragma unroll
            for (int u = 0; u < 4; u++) {
                uint4 t = make_uint4(f2tf(ra[u].x), f2tf(ra[u].y), f2tf(ra[u].z), f2tf(ra[u].w));
                *(uint4*)&As[nx * ASZ + arow * SA + acs + u * 4] = t;
            }
#pragma unroll
            for (int u = 0; u < NB4; u++) {
                uint4 t = make_uint4(f2tf(rb[u].x), f2tf(rb[u].y), f2tf(rb[u].z), f2tf(rb[u].w));
                *(uint4*)&Bs[nx * BSZ + brow * SA + bcs + u * 4] = t;
            }
        }
        __syncthreads();
        cur ^= 1;
    }

#pragma unroll
    for (int i = 0; i < 2; i++) {
        int r0 = bm + m0 + i * 16 + g;
#pragma unroll
        for (int j = 0; j < NFRAG; j++) {
            int cc = bn + n0 + j * 8 + tig * 2;
            float v00 = c[i][j][0], v01 = c[i][j][1];
            float v10 = c[i][j][2], v11 = c[i][j][3];
            if (ROPE) {
                int hc = cc % DQK;
                if (hc >= DNOPE) {
                    int pi = (hc - DNOPE) >> 1;
                    float c0 = g_cos[r0 * 32 + pi], s0 = g_sin[r0 * 32 + pi];
                    float t0 = v00 * c0 - v01 * s0;
                    v01 = v00 * s0 + v01 * c0; v00 = t0;
                    float c1 = g_cos[(r0 + 8) * 32 + pi], s1 = g_sin[(r0 + 8) * 32 + pi];
                    float t1 = v10 * c1 - v11 * s1;
                    v11 = v10 * s1 + v11 * c1; v10 = t1;
                }
            }
            *(float2*)&C[(size_t)r0 * N + cc] = make_float2(v00, v01);
            *(float2*)&C[(size_t)(r0 + 8) * N + cc] = make_float2(v10, v11);
        }
    }
}

// =================================================================
// RoPE tables
// =================================================================
__global__ void rope_table_kernel()
{
    int idx = blockIdx.x * blockDim.x + threadIdx.x;
    int i = idx & 31, t = idx >> 5;
    double inv = pow(10000.0, -(double)(2 * i) / 64.0);
    double sd, cd;
    sincos((double)t * inv, &sd, &cd);
    g_cos[idx] = (float)cd;
    g_sin[idx] = (float)sd;
}

// LayerNorm(kv) + RoPE(k_pe)
__global__ void ln_ropek_kernel(
    const float* __restrict__ kvf, const float* __restrict__ gamma,
    const float* __restrict__ beta, float* __restrict__ kvn,
    float* __restrict__ kpe)
{
    int row = blockIdx.x, tid = threadIdx.x;
    __shared__ float red[16];
    float a = kvf[row * KVF + tid];
    float b = kvf[row * KVF + 256 + tid];
    float s1 = a + b, s2 = a * a + b * b;
#pragma unroll
    for (int off = 16; off; off >>= 1) {
        s1 += __shfl_xor_sync(0xffffffffu, s1, off);
        s2 += __shfl_xor_sync(0xffffffffu, s2, off);
    }
    if ((tid & 31) == 0) { red[tid >> 5] = s1; red[8 + (tid >> 5)] = s2; }
    __syncthreads();
    float t1 = 0.f, t2 = 0.f;
#pragma unroll
    for (int i = 0; i < 8; i++) { t1 += red[i]; t2 += red[8 + i]; }
    float mean = t1 * (1.f / 512.f);
    float var  = t2 * (1.f / 512.f) - mean * mean;
    float rstd = rsqrtf(var + 1e-5f);
    kvn[row * RANK + tid]       = (a - mean) * rstd * gamma[tid] + beta[tid];
    kvn[row * RANK + 256 + tid] = (b - mean) * rstd * gamma[256 + tid] + beta[256 + tid];
    if (tid < 32) {
        int i = tid;
        float c = g_cos[row * 32 + i], s = g_sin[row * 32 + i];
        float x1 = kvf[row * KVF + RANK + 2 * i];
        float x2 = kvf[row * KVF + RANK + 2 * i + 1];
        kpe[row * DROPE + 2 * i]     = x1 * c - x2 * s;
        kpe[row * DROPE + 2 * i + 1] = x1 * s + x2 * c;
    }
}

// =================================================================
// Flash attention v4: q-tile 128 x kv-tile 64, 8 warps all in M.
// KEY: every S row is produced, softmax-reduced, and consumed by the
// SAME warp -> softmax phase needs only __syncwarp(), not block
// barriers. Block barriers remain only around the shared K/V tile.
// =================================================================
#define SQ  196
#define SV  136
#define SSP 68
#define QR  128
#define ATTN_SMEM_BYTES ((QR*SQ + 64*SQ + 64*SV + QR*SSP + 3*QR) * 4)

__global__ void __launch_bounds__(256, 1) attn_kernel(
    const float* __restrict__ q, const float* __restrict__ kvb,
    const float* __restrict__ kpe, float* __restrict__ outp)
{
    extern __shared__ unsigned sm[];
    unsigned* Qs = sm;                    // [128][196] tf32 bits
    unsigned* Ks = Qs + QR * SQ;          // [64][196]
    unsigned* Vs = Ks + 64 * SQ;          // [64][136]
    float* Ssm = (float*)(Vs + 64 * SV);  // [128][68]
    float* m_s = Ssm + QR * SSP;          // [128]
    float* l_s = m_s + QR;                // [128]
    float* al  = l_s + QR;                // [128]

    const int tid = threadIdx.x;
    const int lane = tid & 31, w = tid >> 5;
    const int g = lane >> 2, tig = lane & 3;
    const int m0 = w * 16;                 // warp q-row base (0..112)
    const int h  = blockIdx.y;
    const int iq = (int)(gridDim.x - 1) - (int)blockIdx.x; // big tiles first
    const int q0 = iq * QR;
    const int lr = tid >> 2;               // 0..63   (K/V loads)
    const int seg = tid & 3;               // 0..3
    const int qr = tid >> 1;               // 0..127  (Q load / softmax)
    const int qs = tid & 1;                // 0..1

    // ---- load Q tile (128 x 192), row-major tf32 ----
    {
        const float* src = q + (size_t)(q0 + qr) * QSTRIDE + h * DQK + qs * 96;
#pragma unroll
        for (int u = 0; u < 24; u++) {
            float4 v = *(const float4*)(src + u * 4);
            uint4 t = make_uint4(f2tf(v.x), f2tf(v.y), f2tf(v.z), f2tf(v.w));
            *(uint4*)&Qs[qr * SQ + qs * 96 + u * 4] = t;
        }
    }
    if (tid < QR) { m_s[tid] = -INFINITY; l_s[tid] = 0.f; }

    float o[16][4] = {};   // PV accumulators

    const int jmax = 2 * iq + 1;
    for (int jt = 0; jt <= jmax; jt++) {
        __syncthreads();   // all warps done reading prev K/V (and init, iter 0)

        // ---- load K (k_nope | k_pe) + V tiles, tf32 at store ----
        {
            int t = jt * 64 + lr;
            const float* kn = kvb + (size_t)t * KVBSTRIDE + h * 256;
            const float* kp = kpe + (size_t)t * DROPE;
#pragma unroll
            for (int u = 0; u < 12; u++) {
                int k = seg * 48 + u * 4;
                float4 v = (k < 128) ? *(const float4*)(kn + k)
                                     : *(const float4*)(kp + (k - 128));
                uint4 tt = make_uint4(f2tf(v.x), f2tf(v.y), f2tf(v.z), f2tf(v.w));
                *(uint4*)&Ks[lr * SQ + k] = tt;
            }
            const float* vp = kn + 128;
#pragma unroll
            for (int u = 0; u < 8; u++) {
                int cidx = seg * 32 + u * 4;
                float4 v = *(const float4*)(vp + cidx);
                uint4 tt = make_uint4(f2tf(v.x), f2tf(v.y), f2tf(v.z), f2tf(v.w));
                *(uint4*)&Vs[lr * SV + cidx] = tt;
            }
        }
        __syncthreads();   // K/V visible to all warps

        // ---- S = Q K^T (warp tile 16x64, K=192) ----
        float s[8][4] = {};
#pragma unroll
        for (int k0 = 0; k0 < 192; k0 += 8) {
            unsigned a0 = Qs[(m0 + g) * SQ + k0 + tig];
            unsigned a1 = Qs[(m0 + 8 + g) * SQ + k0 + tig];
            unsigned a2 = Qs[(m0 + g) * SQ + k0 + tig + 4];
            unsigned a3 = Qs[(m0 + 8 + g) * SQ + k0 + tig + 4];
#pragma unroll
            for (int j = 0; j < 8; j++) {
                unsigned b0 = Ks[(j * 8 + g) * SQ + k0 + tig];
                unsigned b1 = Ks[(j * 8 + g) * SQ + k0 + tig + 4];
                mma_tf32(s[j], a0, a1, a2, a3, b0, b1);
            }
        }
#pragma unroll
        for (int j = 0; j < 8; j++) {
            int col = j * 8 + tig * 2;
            int gc0 = jt * 64 + col, gc1 = gc0 + 1;
            int gr0 = q0 + m0 + g, gr1 = gr0 + 8;
            float v0 = (gr0 >= gc0) ? s[j][0] * SCALE : -INFINITY;
            float v1 = (gr0 >= gc1) ? s[j][1] * SCALE : -INFINITY;
            float v2 = (gr1 >= gc0) ? s[j][2] * SCALE : -INFINITY;
            float v3 = (gr1 >= gc1) ? s[j][3] * SCALE : -INFINITY;
            *(float2*)&Ssm[(m0 + g) * SSP + col]     = make_float2(v0, v1);
            *(float2*)&Ssm[(m0 + 8 + g) * SSP + col] = make_float2(v2, v3);
        }
        __syncwarp();      // S rows are warp-private: warp-level fence suffices

        // ---- online softmax: 2 lanes per row (32 cols each) ----
        {
            float* row = &Ssm[qr * SSP + qs * 32];
            float mx = -INFINITY;
#pragma unroll
            for (int cI = 0; cI < 32; cI++) mx = fmaxf(mx, row[cI]);
            mx = fmaxf(mx, __shfl_xor_sync(0xffffffffu, mx, 1));
            float mo = m_s[qr];
            float mn = fmaxf(mo, mx);
            float alpha = __expf(mo - mn);
            float sum = 0.f;
#pragma unroll
            for (int cI = 0; cI < 32; cI++) {
                float p = __expf(row[cI] - mn);
                row[cI] = p;
                sum += p;
            }
            sum += __shfl_xor_sync(0xffffffffu, sum, 1);
            if (qs == 0) {
                m_s[qr] = mn;
                al[qr]  = alpha;
                l_s[qr] = l_s[qr] * alpha + sum;
            }
        }
        __syncwarp();      // P + al visible within the owning warp

        // ---- O = O*alpha + P @ V (warp tile 16x128, K=64) ----
        {
            float av0 = al[m0 + g], av1 = al[m0 + 8 + g];
#pragma unroll
            for (int nt = 0; nt < 16; nt++) {
                o[nt][0] *= av0; o[nt][1] *= av0;
                o[nt][2] *= av1; o[nt][3] *= av1;
            }
        }
#pragma unroll
        for (int k0 = 0; k0 < 64; k0 += 8) {
            unsigned a0 = f2tf(Ssm[(m0 + g) * SSP + k0 + tig]);
            unsigned a1 = f2tf(Ssm[(m0 + 8 + g) * SSP + k0 + tig]);
            unsigned a2 = f2tf(Ssm[(m0 + g) * SSP + k0 + tig + 4]);
            unsigned a3 = f2tf(Ssm[(m0 + 8 + g) * SSP + k0 + tig + 4]);
#pragma unroll
            for (int nt = 0; nt < 16; nt++) {
                unsigned b0 = Vs[(k0 + tig) * SV + nt * 8 + g];
                unsigned b1 = Vs[(k0 + tig + 4) * SV + nt * 8 + g];
                mma_tf32(o[nt], a0, a1, a2, a3, b0, b1);
            }
        }
    }
    __syncwarp();          // l_s rows are warp-private

    {
        float inv0 = 1.f / l_s[m0 + g];
        float inv1 = 1.f / l_s[m0 + 8 + g];
        float* d0 = outp + (size_t)(q0 + m0 + g) * OSTRIDE + h * DV;
        float* d1 = outp + (size_t)(q0 + m0 + 8 + g) * OSTRIDE + h * DV;
#pragma unroll
        for (int nt = 0; nt < 16; nt++) {
            int cc = nt * 8 + tig * 2;
            *(float2*)(d0 + cc) = make_float2(o[nt][0] * inv0, o[nt][1] * inv0);
            *(float2*)(d1 + cc) = make_float2(o[nt][2] * inv1, o[nt][3] * inv1);
        }
    }
}

// =================================================================
// launch
// =================================================================
#define GSM8 (2 * (128 * SA + 128 * SA) * 4)
#define GSM4 (2 * (128 * SA + 64 * SA) * 4)

extern "C" void kernel_launch(void* const* d_in, const int* in_sizes, int n_in,
                              void* d_out, int out_size)
{
    const float* x     = (const float*)d_in[0];
    const float* wq    = (const float*)d_in[1];
    const float* wkv_a = (const float*)d_in[2];
    const float* gamma = (const float*)d_in[3];
    const float* beta  = (const float*)d_in[4];
    const float* wkv_b = (const float*)d_in[5];
    const float* wo    = (const float*)d_in[6];
    float* out = (float*)d_out;

    float *gq, *gkvf, *gkvn, *gkpe, *gkvb, *gattn;
    cudaGetSymbolAddress((void**)&gq,    g_q);
    cudaGetSymbolAddress((void**)&gkvf,  g_kvfull);
    cudaGetSymbolAddress((void**)&gkvn,  g_kvn);
    cudaGetSymbolAddress((void**)&gkpe,  g_kpe);
    cudaGetSymbolAddress((void**)&gkvb,  g_kvb);
    cudaGetSymbolAddress((void**)&gattn, g_attn);

    cudaFuncSetAttribute(gemm_tf32<8, true>,
                         cudaFuncAttributeMaxDynamicSharedMemorySize, GSM8);
    cudaFuncSetAttribute(gemm_tf32<8, false>,
                         cudaFuncAttributeMaxDynamicSharedMemorySize, GSM8);
    cudaFuncSetAttribute(gemm_tf32<4, false>,
                         cudaFuncAttributeMaxDynamicSharedMemorySize, GSM4);
    cudaFuncSetAttribute(attn_kernel,
                         cudaFuncAttributeMaxDynamicSharedMemorySize, ATTN_SMEM_BYTES);

    // rope tables
    rope_table_kernel<<<(TT * 32) / 256, 256>>>();
    // q = x @ wq^T (+fused rope on q_pe)   (4096 x 3072, K=2048)
    gemm_tf32<8, true><<<dim3(3072 / 128, TT / 128), 256, GSM8>>>(
        x, wq, gq, TT, 3072, DMODEL);
    // kv_full = x @ wkv_a^T  (4096 x 576, K=2048)
    gemm_tf32<4, false><<<dim3(KVF / 64, TT / 128), 256, GSM4>>>(
        x, wkv_a, gkvf, TT, KVF, DMODEL);
    // layernorm(kv) + rope(k_pe)
    ln_ropek_kernel<<<TT, 256>>>(gkvf, gamma, beta, gkvn, gkpe);
    // kvb = kvn @ wkv_b^T  (4096 x 4096, K=512)
    gemm_tf32<8, false><<<dim3(KVBSTRIDE / 128, TT / 128), 256, GSM8>>>(
        gkvn, wkv_b, gkvb, TT, KVBSTRIDE, RANK);
    // attention (q-tile 128)
    attn_kernel<<<dim3(TT / QR, NH), 256, ATTN_SMEM_BYTES>>>(gq, gkvb, gkpe, gattn);
    // out = attn @ wo^T  (4096 x 2048, K=2048)
    gemm_tf32<8, false><<<dim3(DMODEL / 128, TT / 128), 256, GSM8>>>(
        gattn, wo, out, TT, DMODEL, DMODEL);
}

// round 10
// speedup vs baseline: 1.1863x; 1.0001x over previous
#include <cuda_runtime.h>
#include <math.h>

// ---------------- problem constants ----------------
#define TT     4096
#define DMODEL 2048
#define NH     16
#define DQK    192     // 128 nope + 64 rope
#define DNOPE  128
#define DROPE  64
#define DV     128
#define RANK   512
#define KVF    (RANK + DROPE)          // 576
#define QSTRIDE (NH * DQK)             // 3072
#define KVBSTRIDE (NH * (DNOPE + DV))  // 4096
#define OSTRIDE (NH * DV)              // 2048
#define SCALE 0.07216878364870323f     // 192^-0.5

// ---------------- scratch (no cudaMalloc allowed) ----------------
__device__ float g_q[TT * QSTRIDE];
__device__ float g_kvfull[TT * KVF];
__device__ float g_kvn[TT * RANK];
__device__ float g_kpe[TT * DROPE];
__device__ float g_kvb[TT * KVBSTRIDE];
__device__ float g_attn[TT * OSTRIDE];
__device__ float g_cos[TT * 32];
__device__ float g_sin[TT * 32];
// tf32-prerounded copies of inputs (rounded once at producer)
__device__ float g_x[TT * DMODEL];
__device__ float g_wq[3072 * DMODEL];
__device__ float g_wkva[KVF * DMODEL];
__device__ float g_wkvb[KVBSTRIDE * RANK];
__device__ float g_wo[DMODEL * DMODEL];

// ---------------- tf32 / async helpers ----------------
__device__ __forceinline__ unsigned f2tf(float x) {
    unsigned u;
    asm("cvt.rna.tf32.f32 %0, %1;" : "=r"(u) : "f"(x));
    return u;
}
__device__ __forceinline__ float f2tff(float x) {
    return __uint_as_float(f2tf(x));
}
__device__ __forceinline__ void mma_tf32(float c[4],
    unsigned a0, unsigned a1, unsigned a2, unsigned a3,
    unsigned b0, unsigned b1)
{
    asm volatile(
        "mma.sync.aligned.m16n8k8.row.col.f32.tf32.tf32.f32 "
        "{%0,%1,%2,%3},{%4,%5,%6,%7},{%8,%9},{%0,%1,%2,%3};"
        : "+f"(c[0]), "+f"(c[1]), "+f"(c[2]), "+f"(c[3])
        : "r"(a0), "r"(a1), "r"(a2), "r"(a3), "r"(b0), "r"(b1));
}
__device__ __forceinline__ void cp16(void* sptr, const void* gptr) {
    unsigned a = (unsigned)__cvta_generic_to_shared(sptr);
    asm volatile("cp.async.cg.shared.global [%0], [%1], 16;" :: "r"(a), "l"(gptr));
}
#define CP_COMMIT() asm volatile("cp.async.commit_group;")

// ---------------- pre-round kernel (rna tf32, elementwise) ----------------
__global__ void round_tf32_kernel(const float* __restrict__ src,
                                  float* __restrict__ dst, int n4)
{
    int i = blockIdx.x * blockDim.x + threadIdx.x;
    if (i < n4) {
        float4 v = ((const float4*)src)[i];
        uint4 t = make_uint4(f2tf(v.x), f2tf(v.y), f2tf(v.z), f2tf(v.w));
        ((uint4*)dst)[i] = t;
    }
}

// =================================================================
// TF32 MMA GEMM v3: 128 x (NFRAG*16) CTA tile, KC=32.
// 3-stage cp.async pipeline (no register staging, no cvt: all inputs
// pre-rounded). One barrier per iteration. 2 CTAs/SM.
// ROUND: rna-round C at store (when consumer is an MMA).
// =================================================================
#define SA 36   // smem k-stride: frag bank = 4g + tig -> conflict-free

template<int NFRAG, bool ROPE, bool ROUND>
__global__ void __launch_bounds__(256, 2) gemm_tf32(
    const float* __restrict__ A, const float* __restrict__ B,
    float* __restrict__ C, int M, int N, int K)
{
    constexpr int BN  = NFRAG * 16;
    constexpr int ASZ = 128 * SA;
    constexpr int BSZ = BN * SA;
    extern __shared__ float smemg[];
    float* As = smemg;                 // [3][ASZ]
    float* Bs = smemg + 3 * ASZ;       // [3][BSZ]

    const int tid = threadIdx.x;
    const int lane = tid & 31, w = tid >> 5;
    const int g = lane >> 2, tig = lane & 3;
    const int bm = blockIdx.y * 128, bn = blockIdx.x * BN;
    const int m0 = (w >> 1) * 32;
    const int n0 = (w & 1) * (BN / 2);

    const int arow = tid >> 1, acs = (tid & 1) * 16;
    constexpr int TPR = 256 / BN;          // threads per B row
    constexpr int BW  = 32 / TPR;          // B floats per thread
    constexpr int NB4 = BW / 4;
    const int brow = tid / TPR, bcs = (tid % TPR) * BW;

    const float* Ap = A + (size_t)(bm + arow) * K + acs;
    const float* Bp = B + (size_t)(bn + brow) * K + bcs;

    const int nsteps = K >> 5;

    auto issue = [&](int st, int k0) {
        float* Ad = As + st * ASZ + arow * SA + acs;
#pragma unroll
        for (int u = 0; u < 4; u++) cp16(Ad + u * 4, Ap + k0 + u * 4);
        float* Bd = Bs + st * BSZ + brow * SA + bcs;
#pragma unroll
        for (int u = 0; u < NB4; u++) cp16(Bd + u * 4, Bp + k0 + u * 4);
        CP_COMMIT();
    };

    issue(0, 0);
    issue(1, 32);

    float c[2][NFRAG][4] = {};

    int st = 0;
    for (int i = 0; i < nsteps; i++) {
        if (i < nsteps - 1) asm volatile("cp.async.wait_group 1;");
        else                asm volatile("cp.async.wait_group 0;");
        __syncthreads();

        const float* Ac = As + st * ASZ;
        const float* Bc = Bs + st * BSZ;
#pragma unroll
        for (int kk = 0; kk < 32; kk += 8) {
            unsigned a[2][4];
#pragma unroll
            for (int ii = 0; ii < 2; ii++) {
                int r = m0 + ii * 16 + g;
                a[ii][0] = __float_as_uint(Ac[r * SA + kk + tig]);
                a[ii][1] = __float_as_uint(Ac[(r + 8) * SA + kk + tig]);
                a[ii][2] = __float_as_uint(Ac[r * SA + kk + tig + 4]);
                a[ii][3] = __float_as_uint(Ac[(r + 8) * SA + kk + tig + 4]);
            }
#pragma unroll
            for (int j = 0; j < NFRAG; j++) {
                unsigned b0 = __float_as_uint(Bc[(n0 + j * 8 + g) * SA + kk + tig]);
                unsigned b1 = __float_as_uint(Bc[(n0 + j * 8 + g) * SA + kk + tig + 4]);
#pragma unroll
                for (int ii = 0; ii < 2; ii++)
                    mma_tf32(c[ii][j], a[ii][0], a[ii][1], a[ii][2], a[ii][3], b0, b1);
            }
        }
        if (i + 2 < nsteps) issue((st + 2) % 3, (i + 2) * 32);
        st = (st + 1) % 3;
    }

    // epilogue (optional fused RoPE on q_pe columns; optional tf32 round)
#pragma unroll
    for (int i = 0; i < 2; i++) {
        int r0 = bm + m0 + i * 16 + g;
#pragma unroll
        for (int j = 0; j < NFRAG; j++) {
            int cc = bn + n0 + j * 8 + tig * 2;
            float v00 = c[i][j][0], v01 = c[i][j][1];
            float v10 = c[i][j][2], v11 = c[i][j][3];
            if (ROPE) {
                int hc = cc % DQK;
                if (hc >= DNOPE) {
                    int pi = (hc - DNOPE) >> 1;
                    float c0 = g_cos[r0 * 32 + pi], s0 = g_sin[r0 * 32 + pi];
                    float t0 = v00 * c0 - v01 * s0;
                    v01 = v00 * s0 + v01 * c0; v00 = t0;
                    float c1 = g_cos[(r0 + 8) * 32 + pi], s1 = g_sin[(r0 + 8) * 32 + pi];
                    float t1 = v10 * c1 - v11 * s1;
                    v11 = v10 * s1 + v11 * c1; v10 = t1;
                }
            }
            if (ROUND) {
                v00 = f2tff(v00); v01 = f2tff(v01);
                v10 = f2tff(v10); v11 = f2tff(v11);
            }
            *(float2*)&C[(size_t)r0 * N + cc] = make_float2(v00, v01);
            *(float2*)&C[(size_t)(r0 + 8) * N + cc] = make_float2(v10, v11);
        }
    }
}

// =================================================================
// RoPE tables
// =================================================================
__global__ void rope_table_kernel()
{
    int idx = blockIdx.x * blockDim.x + threadIdx.x;
    int i = idx & 31, t = idx >> 5;
    double inv = pow(10000.0, -(double)(2 * i) / 64.0);
    double sd, cd;
    sincos((double)t * inv, &sd, &cd);
    g_cos[idx] = (float)cd;
    g_sin[idx] = (float)sd;
}

// LayerNorm(kv) + RoPE(k_pe); outputs pre-rounded to tf32 (both feed MMAs)
__global__ void ln_ropek_kernel(
    const float* __restrict__ kvf, const float* __restrict__ gamma,
    const float* __restrict__ beta, float* __restrict__ kvn,
    float* __restrict__ kpe)
{
    int row = blockIdx.x, tid = threadIdx.x;
    __shared__ float red[16];
    float a = kvf[row * KVF + tid];
    float b = kvf[row * KVF + 256 + tid];
    float s1 = a + b, s2 = a * a + b * b;
#pragma unroll
    for (int off = 16; off; off >>= 1) {
        s1 += __shfl_xor_sync(0xffffffffu, s1, off);
        s2 += __shfl_xor_sync(0xffffffffu, s2, off);
    }
    if ((tid & 31) == 0) { red[tid >> 5] = s1; red[8 + (tid >> 5)] = s2; }
    __syncthreads();
    float t1 = 0.f, t2 = 0.f;
#pragma unroll
    for (int i = 0; i < 8; i++) { t1 += red[i]; t2 += red[8 + i]; }
    float mean = t1 * (1.f / 512.f);
    float var  = t2 * (1.f / 512.f) - mean * mean;
    float rstd = rsqrtf(var + 1e-5f);
    kvn[row * RANK + tid]       = f2tff((a - mean) * rstd * gamma[tid] + beta[tid]);
    kvn[row * RANK + 256 + tid] = f2tff((b - mean) * rstd * gamma[256 + tid] + beta[256 + tid]);
    if (tid < 32) {
        int i = tid;
        float c = g_cos[row * 32 + i], s = g_sin[row * 32 + i];
        float x1 = kvf[row * KVF + RANK + 2 * i];
        float x2 = kvf[row * KVF + RANK + 2 * i + 1];
        kpe[row * DROPE + 2 * i]     = f2tff(x1 * c - x2 * s);
        kpe[row * DROPE + 2 * i + 1] = f2tff(x1 * s + x2 * c);
    }
}

// =================================================================
// Flash attention v5: q-tile 128 x kv-tile 64, 8 warps all in M,
// warp-private softmax. All inputs pre-rounded tf32 -> load path and
// fragment path are cvt-free; P rounded once at softmax store.
// =================================================================
#define SQ  196
#define SV  136
#define SSP 68
#define QR  128
#define ATTN_SMEM_BYTES ((QR*SQ + 64*SQ + 64*SV + QR*SSP + 3*QR) * 4)

__global__ void __launch_bounds__(256, 1) attn_kernel(
    const float* __restrict__ q, const float* __restrict__ kvb,
    const float* __restrict__ kpe, float* __restrict__ outp)
{
    extern __shared__ float sm[];
    float* Qs  = sm;                      // [128][196] tf32-valued
    float* Ks  = Qs + QR * SQ;            // [64][196]
    float* Vs  = Ks + 64 * SQ;            // [64][136]
    float* Ssm = Vs + 64 * SV;            // [128][68]
    float* m_s = Ssm + QR * SSP;          // [128]
    float* l_s = m_s + QR;                // [128]
    float* al  = l_s + QR;                // [128]

    const int tid = threadIdx.x;
    const int lane = tid & 31, w = tid >> 5;
    const int g = lane >> 2, tig = lane & 3;
    const int m0 = w * 16;                 // warp q-row base (0..112)
    const int h  = blockIdx.y;
    const int iq = (int)(gridDim.x - 1) - (int)blockIdx.x; // big tiles first
    const int q0 = iq * QR;
    const int lr = tid >> 2;               // 0..63   (K/V loads)
    const int seg = tid & 3;               // 0..3
    const int qr = tid >> 1;               // 0..127  (Q load / softmax)
    const int qs = tid & 1;                // 0..1

    // ---- load Q tile (128 x 192): plain copy, data pre-rounded ----
    {
        const float* src = q + (size_t)(q0 + qr) * QSTRIDE + h * DQK + qs * 96;
#pragma unroll
        for (int u = 0; u < 24; u++)
            *(float4*)&Qs[qr * SQ + qs * 96 + u * 4] = *(const float4*)(src + u * 4);
    }
    if (tid < QR) { m_s[tid] = -INFINITY; l_s[tid] = 0.f; }

    float o[16][4] = {};   // PV accumulators

    const int jmax = 2 * iq + 1;
    for (int jt = 0; jt <= jmax; jt++) {
        __syncthreads();   // all warps done reading prev K/V (and init, iter 0)

        // ---- load K (k_nope | k_pe) + V tiles: plain copies ----
        {
            int t = jt * 64 + lr;
            const float* kn = kvb + (size_t)t * KVBSTRIDE + h * 256;
            const float* kp = kpe + (size_t)t * DROPE;
#pragma unroll
            for (int u = 0; u < 12; u++) {
                int k = seg * 48 + u * 4;
                float4 v = (k < 128) ? *(const float4*)(kn + k)
                                     : *(const float4*)(kp + (k - 128));
                *(float4*)&Ks[lr * SQ + k] = v;
            }
            const float* vp = kn + 128;
#pragma unroll
            for (int u = 0; u < 8; u++) {
                int cidx = seg * 32 + u * 4;
                *(float4*)&Vs[lr * SV + cidx] = *(const float4*)(vp + cidx);
            }
        }
        __syncthreads();   // K/V visible to all warps

        // ---- S = Q K^T (warp tile 16x64, K=192) ----
        float s[8][4] = {};
#pragma unroll
        for (int k0 = 0; k0 < 192; k0 += 8) {
            unsigned a0 = __float_as_uint(Qs[(m0 + g) * SQ + k0 + tig]);
            unsigned a1 = __float_as_uint(Qs[(m0 + 8 + g) * SQ + k0 + tig]);
            unsigned a2 = __float_as_uint(Qs[(m0 + g) * SQ + k0 + tig + 4]);
            unsigned a3 = __float_as_uint(Qs[(m0 + 8 + g) * SQ + k0 + tig + 4]);
#pragma unroll
            for (int j = 0; j < 8; j++) {
                unsigned b0 = __float_as_uint(Ks[(j * 8 + g) * SQ + k0 + tig]);
                unsigned b1 = __float_as_uint(Ks[(j * 8 + g) * SQ + k0 + tig + 4]);
                mma_tf32(s[j], a0, a1, a2, a3, b0, b1);
            }
        }
#pragma unroll
        for (int j = 0; j < 8; j++) {
            int col = j * 8 + tig * 2;
            int gc0 = jt * 64 + col, gc1 = gc0 + 1;
            int gr0 = q0 + m0 + g, gr1 = gr0 + 8;
            float v0 = (gr0 >= gc0) ? s[j][0] * SCALE : -INFINITY;
            float v1 = (gr0 >= gc1) ? s[j][1] * SCALE : -INFINITY;
            float v2 = (gr1 >= gc0) ? s[j][2] * SCALE : -INFINITY;
            float v3 = (gr1 >= gc1) ? s[j][3] * SCALE : -INFINITY;
            *(float2*)&Ssm[(m0 + g) * SSP + col]     = make_float2(v0, v1);
            *(float2*)&Ssm[(m0 + 8 + g) * SSP + col] = make_float2(v2, v3);
        }
        __syncwarp();      // S rows are warp-private

        // ---- online softmax: 2 lanes per row (32 cols each) ----
        {
            float* row = &Ssm[qr * SSP + qs * 32];
            float mx = -INFINITY;
#pragma unroll
            for (int cI = 0; cI < 32; cI++) mx = fmaxf(mx, row[cI]);
            mx = fmaxf(mx, __shfl_xor_sync(0xffffffffu, mx, 1));
            float mo = m_s[qr];
            float mn = fmaxf(mo, mx);
            float alpha = __expf(mo - mn);
            float sum = 0.f;
#pragma unroll
            for (int cI = 0; cI < 32; cI++) {
                float p = __expf(row[cI] - mn);
                row[cI] = f2tff(p);       // P pre-rounded for the PV mma
                sum += p;
            }
            sum += __shfl_xor_sync(0xffffffffu, sum, 1);
            if (qs == 0) {
                m_s[qr] = mn;
                al[qr]  = alpha;
                l_s[qr] = l_s[qr] * alpha + sum;
            }
        }
        __syncwarp();      // P + al visible within the owning warp

        // ---- O = O*alpha + P @ V (warp tile 16x128, K=64) ----
        {
            float av0 = al[m0 + g], av1 = al[m0 + 8 + g];
#pragma unroll
            for (int nt = 0; nt < 16; nt++) {
                o[nt][0] *= av0; o[nt][1] *= av0;
                o[nt][2] *= av1; o[nt][3] *= av1;
            }
        }
#pragma unroll
        for (int k0 = 0; k0 < 64; k0 += 8) {
            unsigned a0 = __float_as_uint(Ssm[(m0 + g) * SSP + k0 + tig]);
            unsigned a1 = __float_as_uint(Ssm[(m0 + 8 + g) * SSP + k0 + tig]);
            unsigned a2 = __float_as_uint(Ssm[(m0 + g) * SSP + k0 + tig + 4]);
            unsigned a3 = __float_as_uint(Ssm[(m0 + 8 + g) * SSP + k0 + tig + 4]);
#pragma unroll
            for (int nt = 0; nt < 16; nt++) {
                unsigned b0 = __float_as_uint(Vs[(k0 + tig) * SV + nt * 8 + g]);
                unsigned b1 = __float_as_uint(Vs[(k0 + tig + 4) * SV + nt * 8 + g]);
                mma_tf32(o[nt], a0, a1, a2, a3, b0, b1);
            }
        }
    }
    __syncwarp();          // l_s rows are warp-private

    {
        float inv0 = 1.f / l_s[m0 + g];
        float inv1 = 1.f / l_s[m0 + 8 + g];
        float* d0 = outp + (size_t)(q0 + m0 + g) * OSTRIDE + h * DV;
        float* d1 = outp + (size_t)(q0 + m0 + 8 + g) * OSTRIDE + h * DV;
#pragma unroll
        for (int nt = 0; nt < 16; nt++) {
            int cc = nt * 8 + tig * 2;
            *(float2*)(d0 + cc) = make_float2(f2tff(o[nt][0] * inv0), f2tff(o[nt][1] * inv0));
            *(float2*)(d1 + cc) = make_float2(f2tff(o[nt][2] * inv1), f2tff(o[nt][3] * inv1));
        }
    }
}

// =================================================================
// launch
// =================================================================
#define GSM3_8 (3 * (128 * SA + 128 * SA) * 4)   // 110592 B
#define GSM3_4 (3 * (128 * SA + 64 * SA) * 4)    // 82944 B

extern "C" void kernel_launch(void* const* d_in, const int* in_sizes, int n_in,
                              void* d_out, int out_size)
{
    const float* x     = (const float*)d_in[0];
    const float* wq    = (const float*)d_in[1];
    const float* wkv_a = (const float*)d_in[2];
    const float* gamma = (const float*)d_in[3];
    const float* beta  = (const float*)d_in[4];
    const float* wkv_b = (const float*)d_in[5];
    const float* wo    = (const float*)d_in[6];
    float* out = (float*)d_out;

    float *gq, *gkvf, *gkvn, *gkpe, *gkvb, *gattn;
    float *gx, *gwq, *gwkva, *gwkvb, *gwo;
    cudaGetSymbolAddress((void**)&gq,    g_q);
    cudaGetSymbolAddress((void**)&gkvf,  g_kvfull);
    cudaGetSymbolAddress((void**)&gkvn,  g_kvn);
    cudaGetSymbolAddress((void**)&gkpe,  g_kpe);
    cudaGetSymbolAddress((void**)&gkvb,  g_kvb);
    cudaGetSymbolAddress((void**)&gattn, g_attn);
    cudaGetSymbolAddress((void**)&gx,    g_x);
    cudaGetSymbolAddress((void**)&gwq,   g_wq);
    cudaGetSymbolAddress((void**)&gwkva, g_wkva);
    cudaGetSymbolAddress((void**)&gwkvb, g_wkvb);
    cudaGetSymbolAddress((void**)&gwo,   g_wo);

    cudaFuncSetAttribute(gemm_tf32<8, true, true>,
                         cudaFuncAttributeMaxDynamicSharedMemorySize, GSM3_8);
    cudaFuncSetAttribute(gemm_tf32<8, false, true>,
                         cudaFuncAttributeMaxDynamicSharedMemorySize, GSM3_8);
    cudaFuncSetAttribute(gemm_tf32<8, false, false>,
                         cudaFuncAttributeMaxDynamicSharedMemorySize, GSM3_8);
    cudaFuncSetAttribute(gemm_tf32<4, false, false>,
                         cudaFuncAttributeMaxDynamicSharedMemorySize, GSM3_4);
    cudaFuncSetAttribute(attn_kernel,
                         cudaFuncAttributeMaxDynamicSharedMemorySize, ATTN_SMEM_BYTES);

    // rope tables + pre-round inputs to tf32 values (rna, once)
    rope_table_kernel<<<(TT * 32) / 256, 256>>>();
    round_tf32_kernel<<<(TT * DMODEL / 4 + 255) / 256, 256>>>(x, gx, TT * DMODEL / 4);
    round_tf32_kernel<<<(3072 * DMODEL / 4 + 255) / 256, 256>>>(wq, gwq, 3072 * DMODEL / 4);
    round_tf32_kernel<<<(KVF * DMODEL / 4 + 255) / 256, 256>>>(wkv_a, gwkva, KVF * DMODEL / 4);
    round_tf32_kernel<<<(KVBSTRIDE * RANK / 4 + 255) / 256, 256>>>(wkv_b, gwkvb, KVBSTRIDE * RANK / 4);
    round_tf32_kernel<<<(DMODEL * DMODEL / 4 + 255) / 256, 256>>>(wo, gwo, DMODEL * DMODEL / 4);

    // q = x @ wq^T (+fused rope; output rounded)   (4096 x 3072, K=2048)
    gemm_tf32<8, true, true><<<dim3(3072 / 128, TT / 128), 256, GSM3_8>>>(
        gx, gwq, gq, TT, 3072, DMODEL);
    // kv_full = x @ wkv_a^T (raw output -> LN)     (4096 x 576, K=2048)
    gemm_tf32<4, false, false><<<dim3(KVF / 64, TT / 128), 256, GSM3_4>>>(
        gx, gwkva, gkvf, TT, KVF, DMODEL);
    // layernorm(kv) + rope(k_pe), outputs rounded
    ln_ropek_kernel<<<TT, 256>>>(gkvf, gamma, beta, gkvn, gkpe);
    // kvb = kvn @ wkv_b^T (output rounded)         (4096 x 4096, K=512)
    gemm_tf32<8, false, true><<<dim3(KVBSTRIDE / 128, TT / 128), 256, GSM3_8>>>(
        gkvn, gwkvb, gkvb, TT, KVBSTRIDE, RANK);
    // attention (q-tile 128; output rounded)
    attn_kernel<<<dim3(TT / QR, NH), 256, ATTN_SMEM_BYTES>>>(gq, gkvb, gkpe, gattn);
    // out = attn @ wo^T (raw final output)         (4096 x 2048, K=2048)
    gemm_tf32<8, false, false><<<dim3(DMODEL / 128, TT / 128), 256, GSM3_8>>>(
        gattn, gwo, out, TT, DMODEL, DMODEL);
}

// round 13
// speedup vs baseline: 1.9294x; 1.6265x over previous
#include <cuda_runtime.h>
#include <cuda_fp16.h>
#include <cstdint>
#include <math.h>

// ---------------- problem constants ----------------
#define TT     4096
#define DMODEL 2048
#define NH     16
#define DQK    192     // 128 nope + 64 rope
#define DNOPE  128
#define DROPE  64
#define DV     128
#define RANK   512
#define KVF    (RANK + DROPE)          // 576
#define QSTRIDE (NH * DQK)             // 3072
#define KVBSTRIDE (NH * (DNOPE + DV))  // 4096
#define OSTRIDE (NH * DV)              // 2048
#define SCALE 0.07216878364870323f     // 192^-0.5

// ---------------- scratch (no cudaMalloc allowed) ----------------
__device__ float g_kvfull[TT * KVF];
__device__ float g_kvbv[TT * OSTRIDE];     // V part, tf32-valued fp32
__device__ float g_cos[TT * 32];
__device__ float g_sin[TT * 32];
__device__ __half g_qh[TT * QSTRIDE];
__device__ __half g_kvbh[TT * KVBSTRIDE];
__device__ __half g_kpeh[TT * DROPE];
__device__ __half g_xh[TT * DMODEL];
__device__ __half g_wqh[3072 * DMODEL];
__device__ __half g_wkvah[KVF * DMODEL];
__device__ __half g_wkvbh[KVBSTRIDE * RANK];
__device__ __half g_woh[DMODEL * DMODEL];
__device__ __half g_kvnh[TT * RANK];
__device__ __half g_ah[TT * OSTRIDE];

// ---------------- helpers ----------------
__device__ __forceinline__ unsigned f2tf(float x) {
    unsigned u;
    asm("cvt.rna.tf32.f32 %0, %1;" : "=r"(u) : "f"(x));
    return u;
}
__device__ __forceinline__ float f2tff(float x) { return __uint_as_float(f2tf(x)); }

__device__ __forceinline__ void mma_fp16(float c[4],
    unsigned a0, unsigned a1, unsigned a2, unsigned a3,
    unsigned b0, unsigned b1)
{
    asm volatile(
        "mma.sync.aligned.m16n8k16.row.col.f32.f16.f16.f32 "
        "{%0,%1,%2,%3},{%4,%5,%6,%7},{%8,%9},{%0,%1,%2,%3};"
        : "+f"(c[0]), "+f"(c[1]), "+f"(c[2]), "+f"(c[3])
        : "r"(a0), "r"(a1), "r"(a2), "r"(a3), "r"(b0), "r"(b1));
}
__device__ __forceinline__ void mma_tf32(float c[4],
    unsigned a0, unsigned a1, unsigned a2, unsigned a3,
    unsigned b0, unsigned b1)
{
    asm volatile(
        "mma.sync.aligned.m16n8k8.row.col.f32.tf32.tf32.f32 "
        "{%0,%1,%2,%3},{%4,%5,%6,%7},{%8,%9},{%0,%1,%2,%3};"
        : "+f"(c[0]), "+f"(c[1]), "+f"(c[2]), "+f"(c[3])
        : "r"(a0), "r"(a1), "r"(a2), "r"(a3), "r"(b0), "r"(b1));
}
__device__ __forceinline__ void cp16(void* sptr, const void* gptr) {
    unsigned a = (unsigned)__cvta_generic_to_shared(sptr);
    asm volatile("cp.async.cg.shared.global [%0], [%1], 16;" :: "r"(a), "l"(gptr));
}
#define CP_COMMIT() asm volatile("cp.async.commit_group;")

// ---------------- elementwise preprocessing ----------------
__global__ void tohalf_kernel(const float* __restrict__ src,
                              __half* __restrict__ dst, int n4)
{
    int i = blockIdx.x * blockDim.x + threadIdx.x;
    if (i < n4) {
        float4 v = ((const float4*)src)[i];
        ((__half2*)dst)[2 * i]     = __floats2half2_rn(v.x, v.y);
        ((__half2*)dst)[2 * i + 1] = __floats2half2_rn(v.z, v.w);
    }
}

__global__ void rope_table_kernel()
{
    int idx = blockIdx.x * blockDim.x + threadIdx.x;   // < TT*32
    int i = idx & 31, t = idx >> 5;
    double inv = pow(10000.0, -(double)(2 * i) / 64.0);
    double sd, cd;
    sincos((double)t * inv, &sd, &cd);
    g_cos[idx] = (float)cd;
    g_sin[idx] = (float)sd;
}

// =================================================================
// fp16 MMA GEMM: C[M,N] = A[M,K] @ B[N,K]^T. CTA tile 128 x (NFRAG*16),
// KC=64, 3-stage cp.async pipeline, 2 CTAs/SM. stride 72 halves.
// MODE 0: fp32 raw out. MODE 1: rope(q_pe) + fp16 out.
// MODE 2: fp16 out (full) + fp32 tf32-rounded V-columns out.
// =================================================================
#define SH   72           // smem k-stride in halves (36 b32 == 4 mod 32)
#define SH32 36

template<int NFRAG, int MODE>
__global__ void __launch_bounds__(256, 2) gemm_h(
    const __half* __restrict__ A, const __half* __restrict__ B,
    float* __restrict__ Cf, __half* __restrict__ Ch,
    float* __restrict__ Cv, int N, int K)
{
    constexpr int BN   = NFRAG * 16;
    constexpr int ASZH = 128 * SH;       // halves per A stage
    constexpr int BSZH = BN * SH;
    extern __shared__ __half smh[];
    __half* As = smh;                    // [3][ASZH]
    __half* Bs = smh + 3 * ASZH;         // [3][BSZH]

    const int tid = threadIdx.x;
    const int lane = tid & 31, w = tid >> 5;
    const int g = lane >> 2, tig = lane & 3;
    const int bm = blockIdx.y * 128, bn = blockIdx.x * BN;
    const int m0 = (w >> 1) * 32;
    const int n0 = (w & 1) * (BN / 2);

    // loaders: KC=64 halves (128 B) per row
    const int arow = tid >> 1, acs = (tid & 1) * 32;       // 2 thr/row, 32 halves
    constexpr int TPR = 256 / BN;                          // threads per B row
    constexpr int BW  = 64 / TPR;                          // halves per thread
    constexpr int NB16 = BW / 8;                           // 16B chunks
    const int brow = tid / TPR, bcs = (tid % TPR) * BW;

    const __half* Ap = A + (size_t)(bm + arow) * K + acs;
    const __half* Bp = B + (size_t)(bn + brow) * K + bcs;

    const int nsteps = K >> 6;

    auto issue = [&](int st, int k0) {
        __half* Ad = As + st * ASZH + arow * SH + acs;
#pragma unroll
        for (int u = 0; u < 4; u++) cp16(Ad + u * 8, Ap + k0 + u * 8);
        __half* Bd = Bs + st * BSZH + brow * SH + bcs;
#pragma unroll
        for (int u = 0; u < NB16; u++) cp16(Bd + u * 8, Bp + k0 + u * 8);
        CP_COMMIT();
    };

    issue(0, 0);
    issue(1, 64);

    float c[2][NFRAG][4] = {};

    int st = 0;
    for (int i = 0; i < nsteps; i++) {
        if (i < nsteps - 1) asm volatile("cp.async.wait_group 1;");
        else                asm volatile("cp.async.wait_group 0;");
        __syncthreads();

        const unsigned* Ac = (const unsigned*)(As + st * ASZH);
        const unsigned* Bc = (const unsigned*)(Bs + st * BSZH);
#pragma unroll
        for (int ks = 0; ks < 4; ks++) {       // 4 k16-steps per stage
            unsigned a[2][4];
#pragma unroll
            for (int ii = 0; ii < 2; ii++) {
                int r = m0 + ii * 16 + g;
                int idx = r * SH32 + ks * 8 + tig;
                a[ii][0] = Ac[idx];
                a[ii][1] = Ac[idx + 8 * SH32];
                a[ii][2] = Ac[idx + 4];
                a[ii][3] = Ac[idx + 8 * SH32 + 4];
            }
#pragma unroll
            for (int j = 0; j < NFRAG; j++) {
                int bidx = (n0 + j * 8 + g) * SH32 + ks * 8 + tig;
                unsigned b0 = Bc[bidx], b1 = Bc[bidx + 4];
#pragma unroll
                for (int ii = 0; ii < 2; ii++)
                    mma_fp16(c[ii][j], a[ii][0], a[ii][1], a[ii][2], a[ii][3], b0, b1);
            }
        }
        if (i + 2 < nsteps) issue((st + 2) % 3, (i + 2) * 64);
        st = (st + 1) % 3;
    }

    // ---- epilogue ----
#pragma unroll
    for (int i = 0; i < 2; i++) {
        int r0 = bm + m0 + i * 16 + g;
#pragma unroll
        for (int j = 0; j < NFRAG; j++) {
            int cc = bn + n0 + j * 8 + tig * 2;
            float v00 = c[i][j][0], v01 = c[i][j][1];
            float v10 = c[i][j][2], v11 = c[i][j][3];
            if (MODE == 1) {                    // q: rope + fp16
                int hc = cc % DQK;
                if (hc >= DNOPE) {
                    int pi = (hc - DNOPE) >> 1;
                    float c0 = g_cos[r0 * 32 + pi], s0 = g_sin[r0 * 32 + pi];
                    float t0 = v00 * c0 - v01 * s0;
                    v01 = v00 * s0 + v01 * c0; v00 = t0;
                    float c1 = g_cos[(r0 + 8) * 32 + pi], s1 = g_sin[(r0 + 8) * 32 + pi];
                    float t1 = v10 * c1 - v11 * s1;
                    v11 = v10 * s1 + v11 * c1; v10 = t1;
                }
                *(__half2*)&Ch[(size_t)r0 * N + cc] = __floats2half2_rn(v00, v01);
                *(__half2*)&Ch[(size_t)(r0 + 8) * N + cc] = __floats2half2_rn(v10, v11);
            } else if (MODE == 2) {             // kvb: fp16 full + fp32 V cols
                *(__half2*)&Ch[(size_t)r0 * N + cc] = __floats2half2_rn(v00, v01);
                *(__half2*)&Ch[(size_t)(r0 + 8) * N + cc] = __floats2half2_rn(v10, v11);
                int hc = cc & 255;
                if (hc >= 128) {
                    int vc = (cc >> 8) * 128 + hc - 128;
                    *(float2*)&Cv[(size_t)r0 * OSTRIDE + vc] =
                        make_float2(f2tff(v00), f2tff(v01));
                    *(float2*)&Cv[(size_t)(r0 + 8) * OSTRIDE + vc] =
                        make_float2(f2tff(v10), f2tff(v11));
                }
            } else {                            // raw fp32
                *(float2*)&Cf[(size_t)r0 * N + cc] = make_float2(v00, v01);
                *(float2*)&Cf[(size_t)(r0 + 8) * N + cc] = make_float2(v10, v11);
            }
        }
    }
}

// =================================================================
// LayerNorm(kv) -> fp16 kvn; RoPE(k_pe) -> fp16 kpe
// =================================================================
__global__ void ln_ropek_kernel(
    const float* __restrict__ kvf, const float* __restrict__ gamma,
    const float* __restrict__ beta,
    __half* __restrict__ kvnh, __half* __restrict__ kpeh)
{
    int row = blockIdx.x, tid = threadIdx.x;
    __shared__ float red[16];
    float a = kvf[row * KVF + tid];
    float b = kvf[row * KVF + 256 + tid];
    float s1 = a + b, s2 = a * a + b * b;
#pragma unroll
    for (int off = 16; off; off >>= 1) {
        s1 += __shfl_xor_sync(0xffffffffu, s1, off);
        s2 += __shfl_xor_sync(0xffffffffu, s2, off);
    }
    if ((tid & 31) == 0) { red[tid >> 5] = s1; red[8 + (tid >> 5)] = s2; }
    __syncthreads();
    float t1 = 0.f, t2 = 0.f;
#pragma unroll
    for (int i = 0; i < 8; i++) { t1 += red[i]; t2 += red[8 + i]; }
    float mean = t1 * (1.f / 512.f);
    float var  = t2 * (1.f / 512.f) - mean * mean;
    float rstd = rsqrtf(var + 1e-5f);
    kvnh[row * RANK + tid] =
        __float2half_rn((a - mean) * rstd * gamma[tid] + beta[tid]);
    kvnh[row * RANK + 256 + tid] =
        __float2half_rn((b - mean) * rstd * gamma[256 + tid] + beta[256 + tid]);
    if (tid < 32) {
        int i = tid;
        float c = g_cos[row * 32 + i], s = g_sin[row * 32 + i];
        float x1 = kvf[row * KVF + RANK + 2 * i];
        float x2 = kvf[row * KVF + RANK + 2 * i + 1];
        kpeh[row * DROPE + 2 * i]     = __float2half_rn(x1 * c - x2 * s);
        kpeh[row * DROPE + 2 * i + 1] = __float2half_rn(x1 * s + x2 * c);
    }
}

// =================================================================
// Flash attention: q-tile 128 x kv-tile 64, 8 warps in M, warp-private
// softmax. QK^T in fp16 m16n8k16 (Q/K fp16 smem, stride 200 halves);
// PV in tf32 (V fp32 from kvbv). Output fp16 for the wo GEMM.
// =================================================================
#define SQH  200    // Q/K smem stride in halves (100 b32 == 4 mod 32)
#define SV   136
#define SSP  68
#define QR   128
#define ATTN_SMEM_BYTES (QR*SQH*2 + 64*SQH*2 + 64*SV*4 + QR*SSP*4 + 3*QR*4)

__global__ void __launch_bounds__(256, 1) attn_kernel(
    const __half* __restrict__ qh, const __half* __restrict__ kvbh,
    const __half* __restrict__ kpeh, const float* __restrict__ kvbv,
    __half* __restrict__ ah)
{
    extern __shared__ char smb[];
    __half* Qh = (__half*)smb;                  // [128][200]
    __half* Kh = Qh + QR * SQH;                 // [64][200]
    float* Vs  = (float*)(Kh + 64 * SQH);       // [64][136]
    float* Ssm = Vs + 64 * SV;                  // [128][68]
    float* m_s = Ssm + QR * SSP;                // [128]
    float* l_s = m_s + QR;
    float* al  = l_s + QR;

    const int tid = threadIdx.x;
    const int lane = tid & 31, w = tid >> 5;
    const int g = lane >> 2, tig = lane & 3;
    const int m0 = w * 16;                       // warp q-row base
    const int h  = blockIdx.y;
    const int iq = (int)(gridDim.x - 1) - (int)blockIdx.x;  // big tiles first
    const int q0 = iq * QR;
    const int lr = tid >> 2;                     // 0..63  (K/V loads)
    const int seg = tid & 3;                     // 0..3
    const int qr = tid >> 1;                     // 0..127 (Q load / softmax)
    const int qs = tid & 1;                      // 0..1

    // ---- load Q tile (128 x 192 halves) ----
    {
        const __half* src = qh + (size_t)(q0 + qr) * QSTRIDE + h * DQK + qs * 96;
#pragma unroll
        for (int u = 0; u < 12; u++)
            *(uint4*)&Qh[qr * SQH + qs * 96 + u * 8] = *(const uint4*)(src + u * 8);
    }
    if (tid < QR) { m_s[tid] = -INFINITY; l_s[tid] = 0.f; }

    float o[16][4] = {};

    const int jmax = 2 * iq + 1;
    for (int jt = 0; jt <= jmax; jt++) {
        __syncthreads();   // all warps done reading prev K/V (and init, iter 0)

        // ---- load K (fp16: k_nope | k_pe) + V (fp32) tiles ----
        {
            int t = jt * 64 + lr;
            const __half* kn = kvbh + (size_t)t * KVBSTRIDE + h * 256;
            const __half* kp = kpeh + (size_t)t * DROPE;
#pragma unroll
            for (int u = 0; u < 6; u++) {
                int k = seg * 48 + u * 8;
                const __half* src = (k < 128) ? (kn + k) : (kp + (k - 128));
                *(uint4*)&Kh[lr * SQH + k] = *(const uint4*)src;
            }
            const float* vp = kvbv + (size_t)t * OSTRIDE + h * DV;
#pragma unroll
            for (int u = 0; u < 8; u++) {
                int cidx = seg * 32 + u * 4;
                *(float4*)&Vs[lr * SV + cidx] = *(const float4*)(vp + cidx);
            }
        }
        __syncthreads();

        // ---- S = Q K^T, fp16 m16n8k16 (12 k-steps) ----
        float s[8][4] = {};
        const unsigned* Q32 = (const unsigned*)Qh;
        const unsigned* K32 = (const unsigned*)Kh;
#pragma unroll
        for (int k0 = 0; k0 < 96; k0 += 8) {     // b32 units: 16 halves/step
            int ai = (m0 + g) * (SQH / 2) + k0 + tig;
            unsigned a0 = Q32[ai];
            unsigned a2 = Q32[ai + 4];
            unsigned a1 = Q32[ai + 8 * (SQH / 2)];
            unsigned a3 = Q32[ai + 8 * (SQH / 2) + 4];
#pragma unroll
            for (int j = 0; j < 8; j++) {
                int bi = (j * 8 + g) * (SQH / 2) + k0 + tig;
                mma_fp16(s[j], a0, a1, a2, a3, K32[bi], K32[bi + 4]);
            }
        }
#pragma unroll
        for (int j = 0; j < 8; j++) {
            int col = j * 8 + tig * 2;
            int gc0 = jt * 64 + col, gc1 = gc0 + 1;
            int gr0 = q0 + m0 + g, gr1 = gr0 + 8;
            float v0 = (gr0 >= gc0) ? s[j][0] * SCALE : -INFINITY;
            float v1 = (gr0 >= gc1) ? s[j][1] * SCALE : -INFINITY;
            float v2 = (gr1 >= gc0) ? s[j][2] * SCALE : -INFINITY;
            float v3 = (gr1 >= gc1) ? s[j][3] * SCALE : -INFINITY;
            *(float2*)&Ssm[(m0 + g) * SSP + col]     = make_float2(v0, v1);
            *(float2*)&Ssm[(m0 + 8 + g) * SSP + col] = make_float2(v2, v3);
        }
        __syncwarp();      // S rows are warp-private

        // ---- online softmax: 2 lanes per row ----
        {
            float* row = &Ssm[qr * SSP + qs * 32];
            float mx = -INFINITY;
#pragma unroll
            for (int cI = 0; cI < 32; cI++) mx = fmaxf(mx, row[cI]);
            mx = fmaxf(mx, __shfl_xor_sync(0xffffffffu, mx, 1));
            float mo = m_s[qr];
            float mn = fmaxf(mo, mx);
            float alpha = __expf(mo - mn);
            float sum = 0.f;
#pragma unroll
            for (int cI = 0; cI < 32; cI++) {
                float p = __expf(row[cI] - mn);
                row[cI] = f2tff(p);              // tf32-valued for PV
                sum += p;
            }
            sum += __shfl_xor_sync(0xffffffffu, sum, 1);
            if (qs == 0) {
                m_s[qr] = mn;
                al[qr]  = alpha;
                l_s[qr] = l_s[qr] * alpha + sum;
            }
        }
        __syncwarp();

        // ---- O = O*alpha + P @ V, tf32 (warp tile 16x128, K=64) ----
        {
            float av0 = al[m0 + g], av1 = al[m0 + 8 + g];
#pragma unroll
            for (int nt = 0; nt < 16; nt++) {
                o[nt][0] *= av0; o[nt][1] *= av0;
                o[nt][2] *= av1; o[nt][3] *= av1;
            }
        }
#pragma unroll
        for (int k0 = 0; k0 < 64; k0 += 8) {
            unsigned a0 = __float_as_uint(Ssm[(m0 + g) * SSP + k0 + tig]);
            unsigned a1 = __float_as_uint(Ssm[(m0 + 8 + g) * SSP + k0 + tig]);
            unsigned a2 = __float_as_uint(Ssm[(m0 + g) * SSP + k0 + tig + 4]);
            unsigned a3 = __float_as_uint(Ssm[(m0 + 8 + g) * SSP + k0 + tig + 4]);
#pragma unroll
            for (int nt = 0; nt < 16; nt++) {
                unsigned b0 = __float_as_uint(Vs[(k0 + tig) * SV + nt * 8 + g]);
                unsigned b1 = __float_as_uint(Vs[(k0 + tig + 4) * SV + nt * 8 + g]);
                mma_tf32(o[nt], a0, a1, a2, a3, b0, b1);
            }
        }
    }
    __syncwarp();          // l_s rows are warp-private

    {
        float inv0 = 1.f / l_s[m0 + g];
        float inv1 = 1.f / l_s[m0 + 8 + g];
        size_t r0 = (size_t)(q0 + m0 + g) * OSTRIDE + h * DV;
        size_t r1 = (size_t)(q0 + m0 + 8 + g) * OSTRIDE + h * DV;
#pragma unroll
        for (int nt = 0; nt < 16; nt++) {
            int cc = nt * 8 + tig * 2;
            *(__half2*)(ah + r0 + cc) = __floats2half2_rn(o[nt][0] * inv0, o[nt][1] * inv0);
            *(__half2*)(ah + r1 + cc) = __floats2half2_rn(o[nt][2] * inv1, o[nt][3] * inv1);
        }
    }
}

// =================================================================
// launch
// =================================================================
#define GSMH8 (3 * (128 * SH + 128 * SH) * 2)   // 110592 B
#define GSMH4 (3 * (128 * SH + 64 * SH) * 2)    // 82944 B

extern "C" void kernel_launch(void* const* d_in, const int* in_sizes, int n_in,
                              void* d_out, int out_size)
{
    const float* x     = (const float*)d_in[0];
    const float* wq    = (const float*)d_in[1];
    const float* wkv_a = (const float*)d_in[2];
    const float* gamma = (const float*)d_in[3];
    const float* beta  = (const float*)d_in[4];
    const float* wkv_b = (const float*)d_in[5];
    const float* wo    = (const float*)d_in[6];
    float* out = (float*)d_out;

    float *gkvf, *gkvbv;
    __half *qh, *kvbh, *kpeh, *xh, *wqh, *wkvah, *wkvbh, *woh, *kvnh, *ah;
    cudaGetSymbolAddress((void**)&gkvf,  g_kvfull);
    cudaGetSymbolAddress((void**)&gkvbv, g_kvbv);
    cudaGetSymbolAddress((void**)&qh,    g_qh);
    cudaGetSymbolAddress((void**)&kvbh,  g_kvbh);
    cudaGetSymbolAddress((void**)&kpeh,  g_kpeh);
    cudaGetSymbolAddress((void**)&xh,    g_xh);
    cudaGetSymbolAddress((void**)&wqh,   g_wqh);
    cudaGetSymbolAddress((void**)&wkvah, g_wkvah);
    cudaGetSymbolAddress((void**)&wkvbh, g_wkvbh);
    cudaGetSymbolAddress((void**)&woh,   g_woh);
    cudaGetSymbolAddress((void**)&kvnh,  g_kvnh);
    cudaGetSymbolAddress((void**)&ah,    g_ah);

    cudaFuncSetAttribute(gemm_h<8, 1>, cudaFuncAttributeMaxDynamicSharedMemorySize, GSMH8);
    cudaFuncSetAttribute(gemm_h<8, 2>, cudaFuncAttributeMaxDynamicSharedMemorySize, GSMH8);
    cudaFuncSetAttribute(gemm_h<8, 0>, cudaFuncAttributeMaxDynamicSharedMemorySize, GSMH8);
    cudaFuncSetAttribute(gemm_h<4, 0>, cudaFuncAttributeMaxDynamicSharedMemorySize, GSMH4);
    cudaFuncSetAttribute(attn_kernel, cudaFuncAttributeMaxDynamicSharedMemorySize, ATTN_SMEM_BYTES);

    // tables + fp16 operand copies
    rope_table_kernel<<<(TT * 32) / 256, 256>>>();
    tohalf_kernel<<<(TT * DMODEL / 4 + 255) / 256, 256>>>(x, xh, TT * DMODEL / 4);
    tohalf_kernel<<<(3072 * DMODEL / 4 + 255) / 256, 256>>>(wq, wqh, 3072 * DMODEL / 4);
    tohalf_kernel<<<(KVF * DMODEL / 4 + 255) / 256, 256>>>(wkv_a, wkvah, KVF * DMODEL / 4);
    tohalf_kernel<<<(KVBSTRIDE * RANK / 4 + 255) / 256, 256>>>(wkv_b, wkvbh, KVBSTRIDE * RANK / 4);
    tohalf_kernel<<<(DMODEL * DMODEL / 4 + 255) / 256, 256>>>(wo, woh, DMODEL * DMODEL / 4);

    // q = x @ wq^T (+fused rope) -> fp16       4096 x 3072, K=2048
    gemm_h<8, 1><<<dim3(3072 / 128, TT / 128), 256, GSMH8>>>(
        xh, wqh, nullptr, qh, nullptr, 3072, DMODEL);
    // kv_full = x @ wkv_a^T -> fp32            4096 x 576, K=2048
    gemm_h<4, 0><<<dim3(KVF / 64, TT / 128), 256, GSMH4>>>(
        xh, wkvah, gkvf, nullptr, nullptr, KVF, DMODEL);
    // layernorm(kv) -> fp16 kvn; rope(k_pe) -> fp16
    ln_ropek_kernel<<<TT, 256>>>(gkvf, gamma, beta, kvnh, kpeh);
    // kvb = kvn @ wkv_b^T -> fp16 + fp32 V     4096 x 4096, K=512
    gemm_h<8, 2><<<dim3(KVBSTRIDE / 128, TT / 128), 256, GSMH8>>>(
        kvnh, wkvbh, nullptr, kvbh, gkvbv, KVBSTRIDE, RANK);
    // attention -> fp16
    attn_kernel<<<dim3(TT / QR, NH), 256, ATTN_SMEM_BYTES>>>(qh, kvbh, kpeh, gkvbv, ah);
    // out = attn @ wo^T -> fp32                4096 x 2048, K=2048
    gemm_h<8, 0><<<dim3(DMODEL / 128, TT / 128), 256, GSMH8>>>(
        ah, woh, out, nullptr, nullptr, DMODEL, DMODEL);
}

// round 14
// speedup vs baseline: 2.3337x; 1.2095x over previous
#include <cuda_runtime.h>
#include <cuda_fp16.h>
#include <cstdint>
#include <math.h>

// ---------------- problem constants ----------------
#define TT     4096
#define DMODEL 2048
#define NH     16
#define DQK    192     // 128 nope + 64 rope
#define DNOPE  128
#define DROPE  64
#define DV     128
#define RANK   512
#define KVF    (RANK + DROPE)          // 576
#define QSTRIDE (NH * DQK)             // 3072
#define KVBSTRIDE (NH * (DNOPE + DV))  // 4096
#define OSTRIDE (NH * DV)              // 2048
#define SCALE 0.07216878364870323f     // 192^-0.5

// ---------------- scratch (no cudaMalloc allowed) ----------------
__device__ float g_kvfull[TT * KVF];
__device__ float g_cos[TT * 32];
__device__ float g_sin[TT * 32];
__device__ __half g_qh[TT * QSTRIDE];
__device__ __half g_kvbh[TT * KVBSTRIDE];
__device__ __half g_vth[NH * 128 * TT];    // V^T: [h*128+dv][t]
__device__ __half g_kpeh[TT * DROPE];
__device__ __half g_xh[TT * DMODEL];
__device__ __half g_wqh[3072 * DMODEL];
__device__ __half g_wkvah[KVF * DMODEL];
__device__ __half g_wkvbh[KVBSTRIDE * RANK];
__device__ __half g_woh[DMODEL * DMODEL];
__device__ __half g_kvnh[TT * RANK];
__device__ __half g_ah[TT * OSTRIDE];

// ---------------- helpers ----------------
__device__ __forceinline__ void mma_fp16(float c[4],
    unsigned a0, unsigned a1, unsigned a2, unsigned a3,
    unsigned b0, unsigned b1)
{
    asm volatile(
        "mma.sync.aligned.m16n8k16.row.col.f32.f16.f16.f32 "
        "{%0,%1,%2,%3},{%4,%5,%6,%7},{%8,%9},{%0,%1,%2,%3};"
        : "+f"(c[0]), "+f"(c[1]), "+f"(c[2]), "+f"(c[3])
        : "r"(a0), "r"(a1), "r"(a2), "r"(a3), "r"(b0), "r"(b1));
}
__device__ __forceinline__ void cp16(void* sptr, const void* gptr) {
    unsigned a = (unsigned)__cvta_generic_to_shared(sptr);
    asm volatile("cp.async.cg.shared.global [%0], [%1], 16;" :: "r"(a), "l"(gptr));
}
#define CP_COMMIT() asm volatile("cp.async.commit_group;")

// ---------------- elementwise preprocessing ----------------
__global__ void tohalf_kernel(const float* __restrict__ src,
                              __half* __restrict__ dst, int n4)
{
    int i = blockIdx.x * blockDim.x + threadIdx.x;
    if (i < n4) {
        float4 v = ((const float4*)src)[i];
        ((__half2*)dst)[2 * i]     = __floats2half2_rn(v.x, v.y);
        ((__half2*)dst)[2 * i + 1] = __floats2half2_rn(v.z, v.w);
    }
}

__global__ void rope_table_kernel()
{
    int idx = blockIdx.x * blockDim.x + threadIdx.x;   // < TT*32
    int i = idx & 31, t = idx >> 5;
    double inv = pow(10000.0, -(double)(2 * i) / 64.0);
    double sd, cd;
    sincos((double)t * inv, &sd, &cd);
    g_cos[idx] = (float)cd;
    g_sin[idx] = (float)sd;
}

// =================================================================
// fp16 MMA GEMM: C[M,N] = A[M,K] @ B[N,K]^T. CTA tile 128 x (NFRAG*16),
// KC=64, 3-stage cp.async pipeline, 2 CTAs/SM, stride 72 halves.
// MODE 0: fp32 raw out. MODE 1: rope(q_pe) + fp16 out.
// MODE 2: fp16 out (full) + transposed fp16 V^T out.
// =================================================================
#define SH   72           // smem k-stride in halves (36 b32 == 4 mod 32)
#define SH32 36

template<int NFRAG, int MODE>
__global__ void __launch_bounds__(256, 2) gemm_h(
    const __half* __restrict__ A, const __half* __restrict__ B,
    float* __restrict__ Cf, __half* __restrict__ Ch,
    __half* __restrict__ Cvt, int N, int K)
{
    constexpr int BN   = NFRAG * 16;
    constexpr int ASZH = 128 * SH;       // halves per A stage
    constexpr int BSZH = BN * SH;
    extern __shared__ __half smh[];
    __half* As = smh;                    // [3][ASZH]
    __half* Bs = smh + 3 * ASZH;         // [3][BSZH]

    const int tid = threadIdx.x;
    const int lane = tid & 31, w = tid >> 5;
    const int g = lane >> 2, tig = lane & 3;
    const int bm = blockIdx.y * 128, bn = blockIdx.x * BN;
    const int m0 = (w >> 1) * 32;
    const int n0 = (w & 1) * (BN / 2);

    const int arow = tid >> 1, acs = (tid & 1) * 32;       // 2 thr/row
    constexpr int TPR = 256 / BN;
    constexpr int BW  = 64 / TPR;
    constexpr int NB16 = BW / 8;
    const int brow = tid / TPR, bcs = (tid % TPR) * BW;

    const __half* Ap = A + (size_t)(bm + arow) * K + acs;
    const __half* Bp = B + (size_t)(bn + brow) * K + bcs;

    const int nsteps = K >> 6;

    auto issue = [&](int st, int k0) {
        __half* Ad = As + st * ASZH + arow * SH + acs;
#pragma unroll
        for (int u = 0; u < 4; u++) cp16(Ad + u * 8, Ap + k0 + u * 8);
        __half* Bd = Bs + st * BSZH + brow * SH + bcs;
#pragma unroll
        for (int u = 0; u < NB16; u++) cp16(Bd + u * 8, Bp + k0 + u * 8);
        CP_COMMIT();
    };

    issue(0, 0);
    issue(1, 64);

    float c[2][NFRAG][4] = {};

    int st = 0;
    for (int i = 0; i < nsteps; i++) {
        if (i < nsteps - 1) asm volatile("cp.async.wait_group 1;");
        else                asm volatile("cp.async.wait_group 0;");
        __syncthreads();

        const unsigned* Ac = (const unsigned*)(As + st * ASZH);
        const unsigned* Bc = (const unsigned*)(Bs + st * BSZH);
#pragma unroll
        for (int ks = 0; ks < 4; ks++) {
            unsigned a[2][4];
#pragma unroll
            for (int ii = 0; ii < 2; ii++) {
                int r = m0 + ii * 16 + g;
                int idx = r * SH32 + ks * 8 + tig;
                a[ii][0] = Ac[idx];
                a[ii][1] = Ac[idx + 8 * SH32];
                a[ii][2] = Ac[idx + 4];
                a[ii][3] = Ac[idx + 8 * SH32 + 4];
            }
#pragma unroll
            for (int j = 0; j < NFRAG; j++) {
                int bidx = (n0 + j * 8 + g) * SH32 + ks * 8 + tig;
                unsigned b0 = Bc[bidx], b1 = Bc[bidx + 4];
#pragma unroll
                for (int ii = 0; ii < 2; ii++)
                    mma_fp16(c[ii][j], a[ii][0], a[ii][1], a[ii][2], a[ii][3], b0, b1);
            }
        }
        if (i + 2 < nsteps) issue((st + 2) % 3, (i + 2) * 64);
        st = (st + 1) % 3;
    }

    // ---- epilogue ----
#pragma unroll
    for (int i = 0; i < 2; i++) {
        int r0 = bm + m0 + i * 16 + g;
#pragma unroll
        for (int j = 0; j < NFRAG; j++) {
            int cc = bn + n0 + j * 8 + tig * 2;
            float v00 = c[i][j][0], v01 = c[i][j][1];
            float v10 = c[i][j][2], v11 = c[i][j][3];
            if (MODE == 1) {                    // q: rope + fp16
                int hc = cc % DQK;
                if (hc >= DNOPE) {
                    int pi = (hc - DNOPE) >> 1;
                    float c0 = g_cos[r0 * 32 + pi], s0 = g_sin[r0 * 32 + pi];
                    float t0 = v00 * c0 - v01 * s0;
                    v01 = v00 * s0 + v01 * c0; v00 = t0;
                    float c1 = g_cos[(r0 + 8) * 32 + pi], s1 = g_sin[(r0 + 8) * 32 + pi];
                    float t1 = v10 * c1 - v11 * s1;
                    v11 = v10 * s1 + v11 * c1; v10 = t1;
                }
                *(__half2*)&Ch[(size_t)r0 * N + cc] = __floats2half2_rn(v00, v01);
                *(__half2*)&Ch[(size_t)(r0 + 8) * N + cc] = __floats2half2_rn(v10, v11);
            } else if (MODE == 2) {             // kvb: fp16 full + V^T fp16
                *(__half2*)&Ch[(size_t)r0 * N + cc] = __floats2half2_rn(v00, v01);
                *(__half2*)&Ch[(size_t)(r0 + 8) * N + cc] = __floats2half2_rn(v10, v11);
                int hc = cc & 255;
                if (hc >= 128) {
                    int dvg = (cc >> 8) * 128 + (hc - 128);   // h*128 + dv
                    Cvt[(size_t)dvg * TT + r0]           = __float2half_rn(v00);
                    Cvt[(size_t)(dvg + 1) * TT + r0]     = __float2half_rn(v01);
                    Cvt[(size_t)dvg * TT + r0 + 8]       = __float2half_rn(v10);
                    Cvt[(size_t)(dvg + 1) * TT + r0 + 8] = __float2half_rn(v11);
                }
            } else {                            // raw fp32
                *(float2*)&Cf[(size_t)r0 * N + cc] = make_float2(v00, v01);
                *(float2*)&Cf[(size_t)(r0 + 8) * N + cc] = make_float2(v10, v11);
            }
        }
    }
}

// =================================================================
// LayerNorm(kv) -> fp16 kvn; RoPE(k_pe) -> fp16 kpe
// =================================================================
__global__ void ln_ropek_kernel(
    const float* __restrict__ kvf, const float* __restrict__ gamma,
    const float* __restrict__ beta,
    __half* __restrict__ kvnh, __half* __restrict__ kpeh)
{
    int row = blockIdx.x, tid = threadIdx.x;
    __shared__ float red[16];
    float a = kvf[row * KVF + tid];
    float b = kvf[row * KVF + 256 + tid];
    float s1 = a + b, s2 = a * a + b * b;
#pragma unroll
    for (int off = 16; off; off >>= 1) {
        s1 += __shfl_xor_sync(0xffffffffu, s1, off);
        s2 += __shfl_xor_sync(0xffffffffu, s2, off);
    }
    if ((tid & 31) == 0) { red[tid >> 5] = s1; red[8 + (tid >> 5)] = s2; }
    __syncthreads();
    float t1 = 0.f, t2 = 0.f;
#pragma unroll
    for (int i = 0; i < 8; i++) { t1 += red[i]; t2 += red[8 + i]; }
    float mean = t1 * (1.f / 512.f);
    float var  = t2 * (1.f / 512.f) - mean * mean;
    float rstd = rsqrtf(var + 1e-5f);
    kvnh[row * RANK + tid] =
        __float2half_rn((a - mean) * rstd * gamma[tid] + beta[tid]);
    kvnh[row * RANK + 256 + tid] =
        __float2half_rn((b - mean) * rstd * gamma[256 + tid] + beta[256 + tid]);
    if (tid < 32) {
        int i = tid;
        float c = g_cos[row * 32 + i], s = g_sin[row * 32 + i];
        float x1 = kvf[row * KVF + RANK + 2 * i];
        float x2 = kvf[row * KVF + RANK + 2 * i + 1];
        kpeh[row * DROPE + 2 * i]     = __float2half_rn(x1 * c - x2 * s);
        kpeh[row * DROPE + 2 * i + 1] = __float2half_rn(x1 * s + x2 * c);
    }
}

// =================================================================
// Flash attention: q-tile 128 x kv-tile 64, 8 warps in M, warp-private
// softmax. QK^T AND PV in fp16 m16n8k16. V^T tiles loaded coalesced
// from g_vth into [dv][72] smem (fragment indexing == GEMM B path).
// P stored fp16 by softmax. Output fp16 for the wo GEMM.
// =================================================================
#define SQH  200    // Q/K smem stride in halves (100 b32 == 4 mod 32)
#define SVTH 72     // V^T / P stride in halves (36 b32 == 4 mod 32)
#define SSP  68
#define QR   128
#define ATTN_SMEM_BYTES (QR*SQH*2 + 64*SQH*2 + 128*SVTH*2 + QR*SVTH*2 + QR*SSP*4 + 3*QR*4)

__global__ void __launch_bounds__(256, 1) attn_kernel(
    const __half* __restrict__ qh, const __half* __restrict__ kvbh,
    const __half* __restrict__ kpeh, const __half* __restrict__ vth,
    __half* __restrict__ ah)
{
    extern __shared__ char smb[];
    __half* Qh = (__half*)smb;                  // [128][200]
    __half* Kh = Qh + QR * SQH;                 // [64][200]
    __half* Vh = Kh + 64 * SQH;                 // [128][72]  V^T: [dv][kv]
    __half* Ph = Vh + 128 * SVTH;               // [128][72]  P fp16
    float* Ssm = (float*)(Ph + QR * SVTH);      // [128][68]  scores fp32
    float* m_s = Ssm + QR * SSP;                // [128]
    float* l_s = m_s + QR;
    float* al  = l_s + QR;

    const int tid = threadIdx.x;
    const int lane = tid & 31, w = tid >> 5;
    const int g = lane >> 2, tig = lane & 3;
    const int m0 = w * 16;                       // warp q-row base
    const int h  = blockIdx.y;
    const int iq = (int)(gridDim.x - 1) - (int)blockIdx.x;  // big tiles first
    const int q0 = iq * QR;
    const int lr = tid >> 2;                     // 0..63  (K loads)
    const int seg = tid & 3;                     // 0..3
    const int qr = tid >> 1;                     // 0..127 (Q/V loads, softmax)
    const int qs = tid & 1;                      // 0..1

    // ---- load Q tile (128 x 192 halves) ----
    {
        const __half* src = qh + (size_t)(q0 + qr) * QSTRIDE + h * DQK + qs * 96;
#pragma unroll
        for (int u = 0; u < 12; u++)
            *(uint4*)&Qh[qr * SQH + qs * 96 + u * 8] = *(const uint4*)(src + u * 8);
    }
    if (tid < QR) { m_s[tid] = -INFINITY; l_s[tid] = 0.f; }

    float o[16][4] = {};

    const int jmax = 2 * iq + 1;
    for (int jt = 0; jt <= jmax; jt++) {
        __syncthreads();   // all warps done reading prev K/V (and init, iter 0)

        // ---- load K tile (fp16: k_nope | k_pe) ----
        {
            int t = jt * 64 + lr;
            const __half* kn = kvbh + (size_t)t * KVBSTRIDE + h * 256;
            const __half* kp = kpeh + (size_t)t * DROPE;
#pragma unroll
            for (int u = 0; u < 6; u++) {
                int k = seg * 48 + u * 8;
                const __half* src = (k < 128) ? (kn + k) : (kp + (k - 128));
                *(uint4*)&Kh[lr * SQH + k] = *(const uint4*)src;
            }
        }
        // ---- load V^T tile: row dv, 32 halves per thread, coalesced ----
        {
            const __half* vsrc = vth + ((size_t)(h * 128 + qr)) * TT + jt * 64 + qs * 32;
#pragma unroll
            for (int u = 0; u < 4; u++)
                *(uint4*)&Vh[qr * SVTH + qs * 32 + u * 8] = *(const uint4*)(vsrc + u * 8);
        }
        __syncthreads();

        // ---- S = Q K^T, fp16 m16n8k16 (12 k-steps) ----
        float s[8][4] = {};
        const unsigned* Q32 = (const unsigned*)Qh;
        const unsigned* K32 = (const unsigned*)Kh;
#pragma unroll
        for (int k0 = 0; k0 < 96; k0 += 8) {
            int ai = (m0 + g) * (SQH / 2) + k0 + tig;
            unsigned a0 = Q32[ai];
            unsigned a2 = Q32[ai + 4];
            unsigned a1 = Q32[ai + 8 * (SQH / 2)];
            unsigned a3 = Q32[ai + 8 * (SQH / 2) + 4];
#pragma unroll
            for (int j = 0; j < 8; j++) {
                int bi = (j * 8 + g) * (SQH / 2) + k0 + tig;
                mma_fp16(s[j], a0, a1, a2, a3, K32[bi], K32[bi + 4]);
            }
        }
#pragma unroll
        for (int j = 0; j < 8; j++) {
            int col = j * 8 + tig * 2;
            int gc0 = jt * 64 + col, gc1 = gc0 + 1;
            int gr0 = q0 + m0 + g, gr1 = gr0 + 8;
            float v0 = (gr0 >= gc0) ? s[j][0] * SCALE : -INFINITY;
            float v1 = (gr0 >= gc1) ? s[j][1] * SCALE : -INFINITY;
            float v2 = (gr1 >= gc0) ? s[j][2] * SCALE : -INFINITY;
            float v3 = (gr1 >= gc1) ? s[j][3] * SCALE : -INFINITY;
            *(float2*)&Ssm[(m0 + g) * SSP + col]     = make_float2(v0, v1);
            *(float2*)&Ssm[(m0 + 8 + g) * SSP + col] = make_float2(v2, v3);
        }
        __syncwarp();      // S rows are warp-private

        // ---- online softmax: 2 lanes per row; P stored fp16 ----
        {
            float* row = &Ssm[qr * SSP + qs * 32];
            __half2* prow = (__half2*)&Ph[qr * SVTH + qs * 32];
            float mx = -INFINITY;
#pragma unroll
            for (int cI = 0; cI < 32; cI++) mx = fmaxf(mx, row[cI]);
            mx = fmaxf(mx, __shfl_xor_sync(0xffffffffu, mx, 1));
            float mo = m_s[qr];
            float mn = fmaxf(mo, mx);
            float alpha = __expf(mo - mn);
            float sum = 0.f;
#pragma unroll
            for (int cI = 0; cI < 32; cI += 2) {
                float p0 = __expf(row[cI] - mn);
                float p1 = __expf(row[cI + 1] - mn);
                prow[cI >> 1] = __floats2half2_rn(p0, p1);
                sum += p0 + p1;
            }
            sum += __shfl_xor_sync(0xffffffffu, sum, 1);
            if (qs == 0) {
                m_s[qr] = mn;
                al[qr]  = alpha;
                l_s[qr] = l_s[qr] * alpha + sum;
            }
        }
        __syncwarp();

        // ---- O = O*alpha + P @ V, fp16 (warp tile 16x128, K=64) ----
        {
            float av0 = al[m0 + g], av1 = al[m0 + 8 + g];
#pragma unroll
            for (int nt = 0; nt < 16; nt++) {
                o[nt][0] *= av0; o[nt][1] *= av0;
                o[nt][2] *= av1; o[nt][3] *= av1;
            }
        }
        {
            const unsigned* P32 = (const unsigned*)Ph;
            const unsigned* V32 = (const unsigned*)Vh;
#pragma unroll
            for (int ks = 0; ks < 4; ks++) {
                int ai = (m0 + g) * (SVTH / 2) + ks * 8 + tig;
                unsigned a0 = P32[ai];
                unsigned a2 = P32[ai + 4];
                unsigned a1 = P32[ai + 8 * (SVTH / 2)];
                unsigned a3 = P32[ai + 8 * (SVTH / 2) + 4];
#pragma unroll
                for (int nt = 0; nt < 16; nt++) {
                    int bi = (nt * 8 + g) * (SVTH / 2) + ks * 8 + tig;
                    mma_fp16(o[nt], a0, a1, a2, a3, V32[bi], V32[bi + 4]);
                }
            }
        }
    }
    __syncwarp();          // l_s rows are warp-private

    {
        float inv0 = 1.f / l_s[m0 + g];
        float inv1 = 1.f / l_s[m0 + 8 + g];
        size_t r0 = (size_t)(q0 + m0 + g) * OSTRIDE + h * DV;
        size_t r1 = (size_t)(q0 + m0 + 8 + g) * OSTRIDE + h * DV;
#pragma unroll
        for (int nt = 0; nt < 16; nt++) {
            int cc = nt * 8 + tig * 2;
            *(__half2*)(ah + r0 + cc) = __floats2half2_rn(o[nt][0] * inv0, o[nt][1] * inv0);
            *(__half2*)(ah + r1 + cc) = __floats2half2_rn(o[nt][2] * inv1, o[nt][3] * inv1);
        }
    }
}

// =================================================================
// launch
// =================================================================
#define GSMH8 (3 * (128 * SH + 128 * SH) * 2)   // 110592 B
#define GSMH4 (3 * (128 * SH + 64 * SH) * 2)    // 82944 B

extern "C" void kernel_launch(void* const* d_in, const int* in_sizes, int n_in,
                              void* d_out, int out_size)
{
    const float* x     = (const float*)d_in[0];
    const float* wq    = (const float*)d_in[1];
    const float* wkv_a = (const float*)d_in[2];
    const float* gamma = (const float*)d_in[3];
    const float* beta  = (const float*)d_in[4];
    const float* wkv_b = (const float*)d_in[5];
    const float* wo    = (const float*)d_in[6];
    float* out = (float*)d_out;

    float *gkvf;
    __half *qh, *kvbh, *vth, *kpeh, *xh, *wqh, *wkvah, *wkvbh, *woh, *kvnh, *ah;
    cudaGetSymbolAddress((void**)&gkvf,  g_kvfull);
    cudaGetSymbolAddress((void**)&qh,    g_qh);
    cudaGetSymbolAddress((void**)&kvbh,  g_kvbh);
    cudaGetSymbolAddress((void**)&vth,   g_vth);
    cudaGetSymbolAddress((void**)&kpeh,  g_kpeh);
    cudaGetSymbolAddress((void**)&xh,    g_xh);
    cudaGetSymbolAddress((void**)&wqh,   g_wqh);
    cudaGetSymbolAddress((void**)&wkvah, g_wkvah);
    cudaGetSymbolAddress((void**)&wkvbh, g_wkvbh);
    cudaGetSymbolAddress((void**)&woh,   g_woh);
    cudaGetSymbolAddress((void**)&kvnh,  g_kvnh);
    cudaGetSymbolAddress((void**)&ah,    g_ah);

    cudaFuncSetAttribute(gemm_h<8, 1>, cudaFuncAttributeMaxDynamicSharedMemorySize, GSMH8);
    cudaFuncSetAttribute(gemm_h<8, 2>, cudaFuncAttributeMaxDynamicSharedMemorySize, GSMH8);
    cudaFuncSetAttribute(gemm_h<8, 0>, cudaFuncAttributeMaxDynamicSharedMemorySize, GSMH8);
    cudaFuncSetAttribute(gemm_h<4, 0>, cudaFuncAttributeMaxDynamicSharedMemorySize, GSMH4);
    cudaFuncSetAttribute(attn_kernel, cudaFuncAttributeMaxDynamicSharedMemorySize, ATTN_SMEM_BYTES);

    // tables + fp16 operand copies
    rope_table_kernel<<<(TT * 32) / 256, 256>>>();
    tohalf_kernel<<<(TT * DMODEL / 4 + 255) / 256, 256>>>(x, xh, TT * DMODEL / 4);
    tohalf_kernel<<<(3072 * DMODEL / 4 + 255) / 256, 256>>>(wq, wqh, 3072 * DMODEL / 4);
    tohalf_kernel<<<(KVF * DMODEL / 4 + 255) / 256, 256>>>(wkv_a, wkvah, KVF * DMODEL / 4);
    tohalf_kernel<<<(KVBSTRIDE * RANK / 4 + 255) / 256, 256>>>(wkv_b, wkvbh, KVBSTRIDE * RANK / 4);
    tohalf_kernel<<<(DMODEL * DMODEL / 4 + 255) / 256, 256>>>(wo, woh, DMODEL * DMODEL / 4);

    // q = x @ wq^T (+fused rope) -> fp16       4096 x 3072, K=2048
    gemm_h<8, 1><<<dim3(3072 / 128, TT / 128), 256, GSMH8>>>(
        xh, wqh, nullptr, qh, nullptr, 3072, DMODEL);
    // kv_full = x @ wkv_a^T -> fp32            4096 x 576, K=2048
    gemm_h<4, 0><<<dim3(KVF / 64, TT / 128), 256, GSMH4>>>(
        xh, wkvah, gkvf, nullptr, nullptr, KVF, DMODEL);
    // layernorm(kv) -> fp16 kvn; rope(k_pe) -> fp16
    ln_ropek_kernel<<<TT, 256>>>(gkvf, gamma, beta, kvnh, kpeh);
    // kvb = kvn @ wkv_b^T -> fp16 + V^T fp16   4096 x 4096, K=512
    gemm_h<8, 2><<<dim3(KVBSTRIDE / 128, TT / 128), 256, GSMH8>>>(
        kvnh, wkvbh, nullptr, kvbh, vth, KVBSTRIDE, RANK);
    // attention -> fp16
    attn_kernel<<<dim3(TT / QR, NH), 256, ATTN_SMEM_BYTES>>>(qh, kvbh, kpeh, vth, ah);
    // out = attn @ wo^T -> fp32                4096 x 2048, K=2048
    gemm_h<8, 0><<<dim3(DMODEL / 128, TT / 128), 256, GSMH8>>>(
        ah, woh, out, nullptr, nullptr, DMODEL, DMODEL);
}

// round 15
// speedup vs baseline: 2.6612x; 1.1403x over previous
#include <cuda_runtime.h>
#include <cuda_fp16.h>
#include <cstdint>
#include <math.h>

// ---------------- problem constants ----------------
#define TT     4096
#define DMODEL 2048
#define NH     16
#define DQK    192     // 128 nope + 64 rope
#define DNOPE  128
#define DROPE  64
#define DV     128
#define RANK   512
#define KVF    (RANK + DROPE)          // 576
#define QSTRIDE (NH * DQK)             // 3072
#define KVBSTRIDE (NH * (DNOPE + DV))  // 4096
#define OSTRIDE (NH * DV)              // 2048
#define SCALE 0.07216878364870323f     // 192^-0.5

// ---------------- scratch (no cudaMalloc allowed) ----------------
__device__ float g_kvfull[TT * KVF];
__device__ float g_cos[TT * 32];
__device__ float g_sin[TT * 32];
__device__ __half g_qh[TT * QSTRIDE];
__device__ __half g_kvbh[TT * KVBSTRIDE];
__device__ __half g_vth[NH * 128 * TT];    // V^T: [h*128+dv][t]
__device__ __half g_kpeh[TT * DROPE];
__device__ __half g_xh[TT * DMODEL];
__device__ __half g_wqh[3072 * DMODEL];
__device__ __half g_wkvah[KVF * DMODEL];
__device__ __half g_wkvbh[KVBSTRIDE * RANK];
__device__ __half g_woh[DMODEL * DMODEL];
__device__ __half g_kvnh[TT * RANK];
__device__ __half g_ah[TT * OSTRIDE];

// ---------------- helpers ----------------
__device__ __forceinline__ void mma_fp16(float c[4],
    unsigned a0, unsigned a1, unsigned a2, unsigned a3,
    unsigned b0, unsigned b1)
{
    asm volatile(
        "mma.sync.aligned.m16n8k16.row.col.f32.f16.f16.f32 "
        "{%0,%1,%2,%3},{%4,%5,%6,%7},{%8,%9},{%0,%1,%2,%3};"
        : "+f"(c[0]), "+f"(c[1]), "+f"(c[2]), "+f"(c[3])
        : "r"(a0), "r"(a1), "r"(a2), "r"(a3), "r"(b0), "r"(b1));
}
__device__ __forceinline__ void cp16(void* sptr, const void* gptr) {
    unsigned a = (unsigned)__cvta_generic_to_shared(sptr);
    asm volatile("cp.async.cg.shared.global [%0], [%1], 16;" :: "r"(a), "l"(gptr));
}
#define CP_COMMIT() asm volatile("cp.async.commit_group;")
__device__ __forceinline__ unsigned pack2(float x, float y) {
    __half2 h = __floats2half2_rn(x, y);
    return *reinterpret_cast<unsigned*>(&h);
}

// ---------------- elementwise preprocessing ----------------
__global__ void tohalf_kernel(const float* __restrict__ src,
                              __half* __restrict__ dst, int n4)
{
    int i = blockIdx.x * blockDim.x + threadIdx.x;
    if (i < n4) {
        float4 v = ((const float4*)src)[i];
        ((__half2*)dst)[2 * i]     = __floats2half2_rn(v.x, v.y);
        ((__half2*)dst)[2 * i + 1] = __floats2half2_rn(v.z, v.w);
    }
}

__global__ void rope_table_kernel()
{
    int idx = blockIdx.x * blockDim.x + threadIdx.x;   // < TT*32
    int i = idx & 31, t = idx >> 5;
    double inv = pow(10000.0, -(double)(2 * i) / 64.0);
    double sd, cd;
    sincos((double)t * inv, &sd, &cd);
    g_cos[idx] = (float)cd;
    g_sin[idx] = (float)sd;
}

// =================================================================
// fp16 MMA GEMM (unchanged from R14): CTA tile 128 x (NFRAG*16),
// KC=64, 3-stage cp.async, 2 CTAs/SM, stride 72 halves.
// MODE 0: fp32 raw out. MODE 1: rope(q_pe) + fp16 out.
// MODE 2: fp16 out (full) + transposed fp16 V^T out.
// =================================================================
#define SH   72
#define SH32 36

template<int NFRAG, int MODE>
__global__ void __launch_bounds__(256, 2) gemm_h(
    const __half* __restrict__ A, const __half* __restrict__ B,
    float* __restrict__ Cf, __half* __restrict__ Ch,
    __half* __restrict__ Cvt, int N, int K)
{
    constexpr int BN   = NFRAG * 16;
    constexpr int ASZH = 128 * SH;
    constexpr int BSZH = BN * SH;
    extern __shared__ __half smh[];
    __half* As = smh;
    __half* Bs = smh + 3 * ASZH;

    const int tid = threadIdx.x;
    const int lane = tid & 31, w = tid >> 5;
    const int g = lane >> 2, tig = lane & 3;
    const int bm = blockIdx.y * 128, bn = blockIdx.x * BN;
    const int m0 = (w >> 1) * 32;
    const int n0 = (w & 1) * (BN / 2);

    const int arow = tid >> 1, acs = (tid & 1) * 32;
    constexpr int TPR = 256 / BN;
    constexpr int BW  = 64 / TPR;
    constexpr int NB16 = BW / 8;
    const int brow = tid / TPR, bcs = (tid % TPR) * BW;

    const __half* Ap = A + (size_t)(bm + arow) * K + acs;
    const __half* Bp = B + (size_t)(bn + brow) * K + bcs;

    const int nsteps = K >> 6;

    auto issue = [&](int st, int k0) {
        __half* Ad = As + st * ASZH + arow * SH + acs;
#pragma unroll
        for (int u = 0; u < 4; u++) cp16(Ad + u * 8, Ap + k0 + u * 8);
        __half* Bd = Bs + st * BSZH + brow * SH + bcs;
#pragma unroll
        for (int u = 0; u < NB16; u++) cp16(Bd + u * 8, Bp + k0 + u * 8);
        CP_COMMIT();
    };

    issue(0, 0);
    issue(1, 64);

    float c[2][NFRAG][4] = {};

    int st = 0;
    for (int i = 0; i < nsteps; i++) {
        if (i < nsteps - 1) asm volatile("cp.async.wait_group 1;");
        else                asm volatile("cp.async.wait_group 0;");
        __syncthreads();

        const unsigned* Ac = (const unsigned*)(As + st * ASZH);
        const unsigned* Bc = (const unsigned*)(Bs + st * BSZH);
#pragma unroll
        for (int ks = 0; ks < 4; ks++) {
            unsigned a[2][4];
#pragma unroll
            for (int ii = 0; ii < 2; ii++) {
                int r = m0 + ii * 16 + g;
                int idx = r * SH32 + ks * 8 + tig;
                a[ii][0] = Ac[idx];
                a[ii][1] = Ac[idx + 8 * SH32];
                a[ii][2] = Ac[idx + 4];
                a[ii][3] = Ac[idx + 8 * SH32 + 4];
            }
#pragma unroll
            for (int j = 0; j < NFRAG; j++) {
                int bidx = (n0 + j * 8 + g) * SH32 + ks * 8 + tig;
                unsigned b0 = Bc[bidx], b1 = Bc[bidx + 4];
#pragma unroll
                for (int ii = 0; ii < 2; ii++)
                    mma_fp16(c[ii][j], a[ii][0], a[ii][1], a[ii][2], a[ii][3], b0, b1);
            }
        }
        if (i + 2 < nsteps) issue((st + 2) % 3, (i + 2) * 64);
        st = (st + 1) % 3;
    }

#pragma unroll
    for (int i = 0; i < 2; i++) {
        int r0 = bm + m0 + i * 16 + g;
#pragma unroll
        for (int j = 0; j < NFRAG; j++) {
            int cc = bn + n0 + j * 8 + tig * 2;
            float v00 = c[i][j][0], v01 = c[i][j][1];
            float v10 = c[i][j][2], v11 = c[i][j][3];
            if (MODE == 1) {
                int hc = cc % DQK;
                if (hc >= DNOPE) {
                    int pi = (hc - DNOPE) >> 1;
                    float c0 = g_cos[r0 * 32 + pi], s0 = g_sin[r0 * 32 + pi];
                    float t0 = v00 * c0 - v01 * s0;
                    v01 = v00 * s0 + v01 * c0; v00 = t0;
                    float c1 = g_cos[(r0 + 8) * 32 + pi], s1 = g_sin[(r0 + 8) * 32 + pi];
                    float t1 = v10 * c1 - v11 * s1;
                    v11 = v10 * s1 + v11 * c1; v10 = t1;
                }
                *(__half2*)&Ch[(size_t)r0 * N + cc] = __floats2half2_rn(v00, v01);
                *(__half2*)&Ch[(size_t)(r0 + 8) * N + cc] = __floats2half2_rn(v10, v11);
            } else if (MODE == 2) {
                *(__half2*)&Ch[(size_t)r0 * N + cc] = __floats2half2_rn(v00, v01);
                *(__half2*)&Ch[(size_t)(r0 + 8) * N + cc] = __floats2half2_rn(v10, v11);
                int hc = cc & 255;
                if (hc >= 128) {
                    int dvg = (cc >> 8) * 128 + (hc - 128);
                    Cvt[(size_t)dvg * TT + r0]           = __float2half_rn(v00);
                    Cvt[(size_t)(dvg + 1) * TT + r0]     = __float2half_rn(v01);
                    Cvt[(size_t)dvg * TT + r0 + 8]       = __float2half_rn(v10);
                    Cvt[(size_t)(dvg + 1) * TT + r0 + 8] = __float2half_rn(v11);
                }
            } else {
                *(float2*)&Cf[(size_t)r0 * N + cc] = make_float2(v00, v01);
                *(float2*)&Cf[(size_t)(r0 + 8) * N + cc] = make_float2(v10, v11);
            }
        }
    }
}

// =================================================================
// LayerNorm(kv) -> fp16 kvn; RoPE(k_pe) -> fp16 kpe
// =================================================================
__global__ void ln_ropek_kernel(
    const float* __restrict__ kvf, const float* __restrict__ gamma,
    const float* __restrict__ beta,
    __half* __restrict__ kvnh, __half* __restrict__ kpeh)
{
    int row = blockIdx.x, tid = threadIdx.x;
    __shared__ float red[16];
    float a = kvf[row * KVF + tid];
    float b = kvf[row * KVF + 256 + tid];
    float s1 = a + b, s2 = a * a + b * b;
#pragma unroll
    for (int off = 16; off; off >>= 1) {
        s1 += __shfl_xor_sync(0xffffffffu, s1, off);
        s2 += __shfl_xor_sync(0xffffffffu, s2, off);
    }
    if ((tid & 31) == 0) { red[tid >> 5] = s1; red[8 + (tid >> 5)] = s2; }
    __syncthreads();
    float t1 = 0.f, t2 = 0.f;
#pragma unroll
    for (int i = 0; i < 8; i++) { t1 += red[i]; t2 += red[8 + i]; }
    float mean = t1 * (1.f / 512.f);
    float var  = t2 * (1.f / 512.f) - mean * mean;
    float rstd = rsqrtf(var + 1e-5f);
    kvnh[row * RANK + tid] =
        __float2half_rn((a - mean) * rstd * gamma[tid] + beta[tid]);
    kvnh[row * RANK + 256 + tid] =
        __float2half_rn((b - mean) * rstd * gamma[256 + tid] + beta[256 + tid]);
    if (tid < 32) {
        int i = tid;
        float c = g_cos[row * 32 + i], s = g_sin[row * 32 + i];
        float x1 = kvf[row * KVF + RANK + 2 * i];
        float x2 = kvf[row * KVF + RANK + 2 * i + 1];
        kpeh[row * DROPE + 2 * i]     = __float2half_rn(x1 * c - x2 * s);
        kpeh[row * DROPE + 2 * i + 1] = __float2half_rn(x1 * s + x2 * c);
    }
}

// =================================================================
// Flash attention v6: register-resident softmax (FA2-style) + cp.async
// double-buffered K/V^T. q-tile 128 x kv-tile 64, 8 warps in M.
// S C-fragments ARE the P A-fragments (repacked half2 in registers).
// Per-thread m/l/alpha state for 2 rows; quad shfl reductions.
// =================================================================
#define SQH  200    // Q/K smem stride in halves (100 b32 == 4 mod 32)
#define SVTH 72     // V^T stride in halves (36 b32 == 4 mod 32)
#define QR   128
#define KSZH (64 * SQH)
#define VSZH (128 * SVTH)
#define ATTN_SMEM_BYTES ((QR*SQH + 2*KSZH + 2*VSZH) * 2)

__global__ void __launch_bounds__(256, 1) attn_kernel(
    const __half* __restrict__ qh, const __half* __restrict__ kvbh,
    const __half* __restrict__ kpeh, const __half* __restrict__ vth,
    __half* __restrict__ ah)
{
    extern __shared__ char smb[];
    __half* Qh = (__half*)smb;                  // [128][200]
    __half* Kh = Qh + QR * SQH;                 // [2][64][200]
    __half* Vh = Kh + 2 * KSZH;                 // [2][128][72]

    const int tid = threadIdx.x;
    const int lane = tid & 31, w = tid >> 5;
    const int g = lane >> 2, tig = lane & 3;
    const int m0 = w * 16;                       // warp q-row base
    const int h  = blockIdx.y;
    const int iq = (int)(gridDim.x - 1) - (int)blockIdx.x;  // big tiles first
    const int q0 = iq * QR;
    const int lr = tid >> 2;                     // 0..63  (K loads)
    const int seg = tid & 3;                     // 0..3
    const int qr = tid >> 1;                     // 0..127 (Q/V loads)
    const int qs = tid & 1;                      // 0..1

    // ---- issue cp.async for K/V^T tile jt into buffer buf ----
    auto issue_kv = [&](int jt, int buf) {
        int t = jt * 64 + lr;
        const __half* kn = kvbh + (size_t)t * KVBSTRIDE + h * 256;
        const __half* kp = kpeh + (size_t)t * DROPE;
        __half* Kb = Kh + buf * KSZH;
#pragma unroll
        for (int u = 0; u < 6; u++) {
            int k = seg * 48 + u * 8;
            const __half* src = (k < 128) ? (kn + k) : (kp + (k - 128));
            cp16(&Kb[lr * SQH + k], src);
        }
        const __half* vsrc = vth + ((size_t)(h * 128 + qr)) * TT + jt * 64 + qs * 32;
        __half* Vb = Vh + buf * VSZH;
#pragma unroll
        for (int u = 0; u < 4; u++)
            cp16(&Vb[qr * SVTH + qs * 32 + u * 8], vsrc + u * 8);
        CP_COMMIT();
    };

    // prologue: first K/V tile + Q tile
    issue_kv(0, 0);
    {
        const __half* src = qh + (size_t)(q0 + qr) * QSTRIDE + h * DQK + qs * 96;
#pragma unroll
        for (int u = 0; u < 12; u++)
            *(uint4*)&Qh[qr * SQH + qs * 96 + u * 8] = *(const uint4*)(src + u * 8);
    }

    // per-thread softmax state: rows m0+g (0) and m0+8+g (1)
    float mr0 = -INFINITY, mr1 = -INFINITY;
    float lr0 = 0.f, lr1 = 0.f;
    float o[16][4] = {};

    const int jmax = 2 * iq + 1;
    for (int jt = 0; jt <= jmax; jt++) {
        __syncthreads();   // all warps done reading buffer being overwritten
        if (jt < jmax) {
            issue_kv(jt + 1, (jt + 1) & 1);
            asm volatile("cp.async.wait_group 1;");
        } else {
            asm volatile("cp.async.wait_group 0;");
        }
        __syncthreads();   // tile jt visible

        const unsigned* K32 = (const unsigned*)(Kh + (jt & 1) * KSZH);
        const unsigned* V32 = (const unsigned*)(Vh + (jt & 1) * VSZH);
        const unsigned* Q32 = (const unsigned*)Qh;

        // ---- S = Q K^T, fp16 (12 k-steps) ----
        float s[8][4] = {};
#pragma unroll
        for (int k0 = 0; k0 < 96; k0 += 8) {
            int ai = (m0 + g) * (SQH / 2) + k0 + tig;
            unsigned a0 = Q32[ai];
            unsigned a2 = Q32[ai + 4];
            unsigned a1 = Q32[ai + 8 * (SQH / 2)];
            unsigned a3 = Q32[ai + 8 * (SQH / 2) + 4];
#pragma unroll
            for (int j = 0; j < 8; j++) {
                int bi = (j * 8 + g) * (SQH / 2) + k0 + tig;
                mma_fp16(s[j], a0, a1, a2, a3, K32[bi], K32[bi + 4]);
            }
        }

        // ---- mask + scale in registers ----
        {
            int gr0 = q0 + m0 + g, gr1 = gr0 + 8;
#pragma unroll
            for (int j = 0; j < 8; j++) {
                int gc0 = jt * 64 + j * 8 + tig * 2, gc1 = gc0 + 1;
                s[j][0] = (gr0 >= gc0) ? s[j][0] * SCALE : -INFINITY;
                s[j][1] = (gr0 >= gc1) ? s[j][1] * SCALE : -INFINITY;
                s[j][2] = (gr1 >= gc0) ? s[j][2] * SCALE : -INFINITY;
                s[j][3] = (gr1 >= gc1) ? s[j][3] * SCALE : -INFINITY;
            }
        }

        // ---- register softmax: quad shfl reductions ----
        float mx0 = -INFINITY, mx1 = -INFINITY;
#pragma unroll
        for (int j = 0; j < 8; j++) {
            mx0 = fmaxf(mx0, fmaxf(s[j][0], s[j][1]));
            mx1 = fmaxf(mx1, fmaxf(s[j][2], s[j][3]));
        }
        mx0 = fmaxf(mx0, __shfl_xor_sync(0xffffffffu, mx0, 1));
        mx0 = fmaxf(mx0, __shfl_xor_sync(0xffffffffu, mx0, 2));
        mx1 = fmaxf(mx1, __shfl_xor_sync(0xffffffffu, mx1, 1));
        mx1 = fmaxf(mx1, __shfl_xor_sync(0xffffffffu, mx1, 2));
        float mn0 = fmaxf(mr0, mx0), mn1 = fmaxf(mr1, mx1);
        float al0 = __expf(mr0 - mn0), al1 = __expf(mr1 - mn1);
        float sum0 = 0.f, sum1 = 0.f;
#pragma unroll
        for (int j = 0; j < 8; j++) {
            s[j][0] = __expf(s[j][0] - mn0);
            s[j][1] = __expf(s[j][1] - mn0);
            s[j][2] = __expf(s[j][2] - mn1);
            s[j][3] = __expf(s[j][3] - mn1);
            sum0 += s[j][0] + s[j][1];
            sum1 += s[j][2] + s[j][3];
        }
        sum0 += __shfl_xor_sync(0xffffffffu, sum0, 1);
        sum0 += __shfl_xor_sync(0xffffffffu, sum0, 2);
        sum1 += __shfl_xor_sync(0xffffffffu, sum1, 1);
        sum1 += __shfl_xor_sync(0xffffffffu, sum1, 2);
        lr0 = lr0 * al0 + sum0;  mr0 = mn0;
        lr1 = lr1 * al1 + sum1;  mr1 = mn1;

        // ---- rescale O, then O += P @ V (P packed from S frags) ----
#pragma unroll
        for (int nt = 0; nt < 16; nt++) {
            o[nt][0] *= al0; o[nt][1] *= al0;
            o[nt][2] *= al1; o[nt][3] *= al1;
        }
#pragma unroll
        for (int ks = 0; ks < 4; ks++) {
            // C-frags {2ks, 2ks+1} == A-frag of P for k-chunk ks
            unsigned a0 = pack2(s[2 * ks][0],     s[2 * ks][1]);
            unsigned a1 = pack2(s[2 * ks][2],     s[2 * ks][3]);
            unsigned a2 = pack2(s[2 * ks + 1][0], s[2 * ks + 1][1]);
            unsigned a3 = pack2(s[2 * ks + 1][2], s[2 * ks + 1][3]);
#pragma unroll
            for (int nt = 0; nt < 16; nt++) {
                int bi = (nt * 8 + g) * (SVTH / 2) + ks * 8 + tig;
                mma_fp16(o[nt], a0, a1, a2, a3, V32[bi], V32[bi + 4]);
            }
        }
    }

    {
        float inv0 = 1.f / lr0;
        float inv1 = 1.f / lr1;
        size_t r0 = (size_t)(q0 + m0 + g) * OSTRIDE + h * DV;
        size_t r1 = (size_t)(q0 + m0 + 8 + g) * OSTRIDE + h * DV;
#pragma unroll
        for (int nt = 0; nt < 16; nt++) {
            int cc = nt * 8 + tig * 2;
            *(__half2*)(ah + r0 + cc) = __floats2half2_rn(o[nt][0] * inv0, o[nt][1] * inv0);
            *(__half2*)(ah + r1 + cc) = __floats2half2_rn(o[nt][2] * inv1, o[nt][3] * inv1);
        }
    }
}

// =================================================================
// launch
// =================================================================
#define GSMH8 (3 * (128 * SH + 128 * SH) * 2)   // 110592 B
#define GSMH4 (3 * (128 * SH + 64 * SH) * 2)    // 82944 B

extern "C" void kernel_launch(void* const* d_in, const int* in_sizes, int n_in,
                              void* d_out, int out_size)
{
    const float* x     = (const float*)d_in[0];
    const float* wq    = (const float*)d_in[1];
    const float* wkv_a = (const float*)d_in[2];
    const float* gamma = (const float*)d_in[3];
    const float* beta  = (const float*)d_in[4];
    const float* wkv_b = (const float*)d_in[5];
    const float* wo    = (const float*)d_in[6];
    float* out = (float*)d_out;

    float *gkvf;
    __half *qh, *kvbh, *vth, *kpeh, *xh, *wqh, *wkvah, *wkvbh, *woh, *kvnh, *ah;
    cudaGetSymbolAddress((void**)&gkvf,  g_kvfull);
    cudaGetSymbolAddress((void**)&qh,    g_qh);
    cudaGetSymbolAddress((void**)&kvbh,  g_kvbh);
    cudaGetSymbolAddress((void**)&vth,   g_vth);
    cudaGetSymbolAddress((void**)&kpeh,  g_kpeh);
    cudaGetSymbolAddress((void**)&xh,    g_xh);
    cudaGetSymbolAddress((void**)&wqh,   g_wqh);
    cudaGetSymbolAddress((void**)&wkvah, g_wkvah);
    cudaGetSymbolAddress((void**)&wkvbh, g_wkvbh);
    cudaGetSymbolAddress((void**)&woh,   g_woh);
    cudaGetSymbolAddress((void**)&kvnh,  g_kvnh);
    cudaGetSymbolAddress((void**)&ah,    g_ah);

    cudaFuncSetAttribute(gemm_h<8, 1>, cudaFuncAttributeMaxDynamicSharedMemorySize, GSMH8);
    cudaFuncSetAttribute(gemm_h<8, 2>, cudaFuncAttributeMaxDynamicSharedMemorySize, GSMH8);
    cudaFuncSetAttribute(gemm_h<8, 0>, cudaFuncAttributeMaxDynamicSharedMemorySize, GSMH8);
    cudaFuncSetAttribute(gemm_h<4, 0>, cudaFuncAttributeMaxDynamicSharedMemorySize, GSMH4);
    cudaFuncSetAttribute(attn_kernel, cudaFuncAttributeMaxDynamicSharedMemorySize, ATTN_SMEM_BYTES);

    // tables + fp16 operand copies
    rope_table_kernel<<<(TT * 32) / 256, 256>>>();
    tohalf_kernel<<<(TT * DMODEL / 4 + 255) / 256, 256>>>(x, xh, TT * DMODEL / 4);
    tohalf_kernel<<<(3072 * DMODEL / 4 + 255) / 256, 256>>>(wq, wqh, 3072 * DMODEL / 4);
    tohalf_kernel<<<(KVF * DMODEL / 4 + 255) / 256, 256>>>(wkv_a, wkvah, KVF * DMODEL / 4);
    tohalf_kernel<<<(KVBSTRIDE * RANK / 4 + 255) / 256, 256>>>(wkv_b, wkvbh, KVBSTRIDE * RANK / 4);
    tohalf_kernel<<<(DMODEL * DMODEL / 4 + 255) / 256, 256>>>(wo, woh, DMODEL * DMODEL / 4);

    // q = x @ wq^T (+fused rope) -> fp16       4096 x 3072, K=2048
    gemm_h<8, 1><<<dim3(3072 / 128, TT / 128), 256, GSMH8>>>(
        xh, wqh, nullptr, qh, nullptr, 3072, DMODEL);
    // kv_full = x @ wkv_a^T -> fp32            4096 x 576, K=2048
    gemm_h<4, 0><<<dim3(KVF / 64, TT / 128), 256, GSMH4>>>(
        xh, wkvah, gkvf, nullptr, nullptr, KVF, DMODEL);
    // layernorm(kv) -> fp16 kvn; rope(k_pe) -> fp16
    ln_ropek_kernel<<<TT, 256>>>(gkvf, gamma, beta, kvnh, kpeh);
    // kvb = kvn @ wkv_b^T -> fp16 + V^T fp16   4096 x 4096, K=512
    gemm_h<8, 2><<<dim3(KVBSTRIDE / 128, TT / 128), 256, GSMH8>>>(
        kvnh, wkvbh, nullptr, kvbh, vth, KVBSTRIDE, RANK);
    // attention -> fp16
    attn_kernel<<<dim3(TT / QR, NH), 256, ATTN_SMEM_BYTES>>>(qh, kvbh, kpeh, vth, ah);
    // out = attn @ wo^T -> fp32                4096 x 2048, K=2048
    gemm_h<8, 0><<<dim3(DMODEL / 128, TT / 128), 256, GSMH8>>>(
        ah, woh, out, nullptr, nullptr, DMODEL, DMODEL);
}